// round 8
// baseline (speedup 1.0000x reference)
#include <cuda_runtime.h>
#include <cuda_fp16.h>
#include <math.h>
#include <stdint.h>

// ---------------- problem constants ----------------
constexpr int BB = 4, SSEQ = 2048, DD = 1024, FF = 4096;
constexpr int MM = BB * SSEQ;                 // 8192
constexpr long long BSD = (long long)MM * DD; // 8388608

// ---------------- scratch (device globals; no allocation) ----------------
__device__ __half g_xn_h[MM * DD];
__device__ __half g_gate[MM * DD];            // sigmoid(gate_pre), fp16
__device__ float  g_a[MM * DD];               // recurrence coefficient, fp32
__device__ __half g_u_h[MM * DD];             // scan input, fp16
__device__ __half g_cc_h[MM * 2 * DD];        // [conv | griffin_h] fp16
__device__ float  g_xnew[MM * DD];
__device__ __half g_nm_h[MM * DD];
__device__ __half g_hd_h[MM * FF];
__device__ __half g_wt_h[12 * 1024 * 1024];
__device__ float  g_splam[DD];
// chunked-scan partials
constexpr int SCH = 16, SLEN = SSEQ / SCH;
__device__ float g_P[BB * DD * SCH], g_Hp[BB * DD * SCH], g_Cc[BB * DD * SCH];

// ---------------- helpers ----------------
__device__ __forceinline__ uint32_t s2u(const void* p) {
    uint32_t a;
    asm("{ .reg .u64 t; cvta.to.shared.u64 t, %1; cvt.u32.u64 %0, t; }" : "=r"(a) : "l"(p));
    return a;
}
__device__ __forceinline__ void cpasync16(uint32_t saddr, const void* g) {
    asm volatile("cp.async.cg.shared.global [%0], [%1], 16;" :: "r"(saddr), "l"(g));
}
__device__ __forceinline__ void cp_commit() {
    asm volatile("cp.async.commit_group;" ::: "memory");
}
template <int N>
__device__ __forceinline__ void cp_wait() {
    asm volatile("cp.async.wait_group %0;" :: "n"(N) : "memory");
}
__device__ __forceinline__ void ldsm4(uint32_t* r, uint32_t addr) {
    asm volatile("ldmatrix.sync.aligned.m8n8.x4.shared.b16 {%0,%1,%2,%3}, [%4];"
                 : "=r"(r[0]), "=r"(r[1]), "=r"(r[2]), "=r"(r[3]) : "r"(addr));
}
__device__ __forceinline__ void mma16816(float* d, const uint32_t* a, const uint32_t* b) {
    asm volatile(
        "mma.sync.aligned.m16n8k16.row.col.f32.f16.f16.f32 "
        "{%0,%1,%2,%3}, {%4,%5,%6,%7}, {%8,%9}, {%0,%1,%2,%3};"
        : "+f"(d[0]), "+f"(d[1]), "+f"(d[2]), "+f"(d[3])
        : "r"(a[0]), "r"(a[1]), "r"(a[2]), "r"(a[3]), "r"(b[0]), "r"(b[1]));
}

// ------- merged weight transpose: all 5 weights, one launch -------
__global__ void transpose_all(const float* __restrict__ Wg, const float* __restrict__ Wa,
                              const float* __restrict__ Wo, const float* __restrict__ W1,
                              const float* __restrict__ W2, __half* __restrict__ out) {
    int b = blockIdx.x;
    const float* W;
    int K, N;
    size_t off;
    int tile;
    if (b < 1024)      { W = Wg; K = 1024; N = 1024; off = 0;               tile = b; }
    else if (b < 2048) { W = Wa; K = 1024; N = 1024; off = (size_t)1 << 20; tile = b - 1024; }
    else if (b < 4096) { W = Wo; K = 2048; N = 1024; off = (size_t)2 << 20; tile = b - 2048; }
    else if (b < 8192) { W = W1; K = 1024; N = 4096; off = (size_t)4 << 20; tile = b - 4096; }
    else               { W = W2; K = 4096; N = 1024; off = (size_t)8 << 20; tile = b - 8192; }
    int ntn = N >> 5;
    int n0 = (tile % ntn) * 32, k0 = (tile / ntn) * 32;
    __half* oh = out + off;

    __shared__ float t[32][33];
    int tid = threadIdx.x;
    #pragma unroll
    for (int i = 0; i < 4; i++) {
        int idx = tid + i * 256;
        int kr = idx >> 5, nc = idx & 31;
        t[kr][nc] = W[(size_t)(k0 + kr) * N + n0 + nc];
    }
    __syncthreads();
    #pragma unroll
    for (int i = 0; i < 2; i++) {
        int idx = tid + i * 256;
        int nr = idx >> 4, kp = idx & 15;
        float v0 = t[kp * 2][nr], v1 = t[kp * 2 + 1][nr];
        size_t o = (size_t)(n0 + nr) * K + k0 + kp * 2;
        *(__half2*)(oh + o) = __halves2half2(__float2half_rn(v0), __float2half_rn(v1));
    }
}

// ---------------- rmsnorm -> fp16 ----------------
__global__ void rmsnorm_h(const float* __restrict__ in, const float* __restrict__ w,
                          __half* __restrict__ oh) {
    int row = blockIdx.x;
    const float4* ip = (const float4*)(in + (size_t)row * DD);
    float4 v = ip[threadIdx.x];
    float ss = v.x * v.x + v.y * v.y + v.z * v.z + v.w * v.w;
    #pragma unroll
    for (int o = 16; o > 0; o >>= 1) ss += __shfl_xor_sync(0xffffffffu, ss, o);
    __shared__ float ws[8];
    int lane = threadIdx.x & 31, wid = threadIdx.x >> 5;
    if (lane == 0) ws[wid] = ss;
    __syncthreads();
    if (wid == 0) {
        float s = (lane < 8) ? ws[lane] : 0.f;
        #pragma unroll
        for (int o = 4; o > 0; o >>= 1) s += __shfl_xor_sync(0xffffffffu, s, o);
        if (lane == 0) ws[0] = s;
    }
    __syncthreads();
    float rms = rsqrtf(ws[0] * (1.0f / DD) + 1e-6f);
    float4 wv = ((const float4*)w)[threadIdx.x];
    size_t o0 = (size_t)row * DD + threadIdx.x * 4;
    *(__half2*)(oh + o0)     = __halves2half2(__float2half_rn(v.x * rms * wv.x),
                                              __float2half_rn(v.y * rms * wv.y));
    *(__half2*)(oh + o0 + 2) = __halves2half2(__float2half_rn(v.z * rms * wv.z),
                                              __float2half_rn(v.w * rms * wv.w));
}

// ---------------- splam[d] = 8 * softplus(lam[d]) ----------------
__global__ void splam_kernel(const float* __restrict__ lam) {
    int d = blockIdx.x * blockDim.x + threadIdx.x;
    if (d < DD) {
        float l = lam[d];
        float sp = (l > 20.f) ? l : log1pf(expf(l));
        g_splam[d] = 8.0f * sp;
    }
}

// ------- fused: conv + u + scan chunk-partials (thread = b,ch,d) -------
__global__ void gscan1_kernel(const float* __restrict__ ck, const float* __restrict__ cb) {
    int gid = blockIdx.x * 256 + threadIdx.x;      // (b*SCH + ch)*DD + d
    int d = gid & (DD - 1);
    int ch = (gid >> 10) & (SCH - 1);
    int b = gid >> 14;
    float4 kv = ((const float4*)ck)[d];
    float cbias = cb[d];

    long long r0 = (long long)b * SSEQ + ch * SLEN;
    long long xbase = r0 * DD + d;
    float xm1 = 0.f, xm2 = 0.f, xm3 = 0.f;
    if (ch > 0) {
        xm1 = __half2float(g_xn_h[xbase - DD]);
        xm2 = __half2float(g_xn_h[xbase - 2 * DD]);
        xm3 = __half2float(g_xn_h[xbase - 3 * DD]);
    }
    float p = 1.f, h = 0.f;
    #pragma unroll 4
    for (int t = 0; t < SLEN; t++) {
        long long i = xbase + (long long)t * DD;
        long long r = r0 + t;
        float xn = __half2float(g_xn_h[i]);
        float conv = cbias + kv.x * xn + kv.y * xm1 + kv.z * xm2 + kv.w * xm3;
        float gate = __half2float(g_gate[i]);
        float a = g_a[i];
        float u = sqrtf(fmaxf(1.f - a * a, 0.f)) * gate * xn;
        g_cc_h[r * (2 * DD) + d] = __float2half_rn(conv);
        g_u_h[i] = __float2half_rn(u);
        p *= a;
        h = fmaf(a, h, u);
        xm3 = xm2; xm2 = xm1; xm1 = xn;
    }
    g_P[gid] = p;
    g_Hp[gid] = h;
}

__global__ void scan_part2() {
    int c = blockIdx.x * 256 + threadIdx.x;
    int b = c >> 10, d = c & (DD - 1);
    float carry = 0.f;
    #pragma unroll
    for (int ch = 0; ch < SCH; ch++) {
        int i = (b * SCH + ch) * DD + d;
        g_Cc[i] = carry;
        carry = fmaf(g_P[i], carry, g_Hp[i]);
    }
}
__global__ void scan_part3() {
    int gid = blockIdx.x * 256 + threadIdx.x;
    int d = gid & (DD - 1);
    int ch = (gid >> 10) & (SCH - 1);
    int b = gid >> 14;
    long long base = ((long long)b * SSEQ + ch * SLEN) * DD + d;
    float h = g_Cc[gid];
    #pragma unroll 4
    for (int t = 0; t < SLEN; t++) {
        long long idx = base + (long long)t * DD;
        h = fmaf(g_a[idx], h, __half2float(g_u_h[idx]));
        long long row = (long long)b * SSEQ + ch * SLEN + t;
        g_cc_h[row * (2 * DD) + DD + d] = __float2half_rn(h);
    }
}

// ------- HMMA GEMM: 128x256 CTA tile, 64x64 warp tiles, BK=32, 3-stage -------
// grid: x = N-blocks (256 wide), y = M-blocks (128 tall)
// EPI: 0 plain fp32; 1 mixer; 2 gelu->fp16; 3 +bias+aux residual;
//      4 gating (gate->fp16 o_hi, a=exp(-splam*sigmoid)->fp32 C, N-stride 1024)
constexpr int STG = 24576;           // A 8K | B 16K
constexpr int GEMM_SMEM = 3 * STG;   // 72 KB

template <int EPI>
__global__ void __launch_bounds__(256, 1)
hgemm(const __half* __restrict__ Ah, const __half* __restrict__ Bh,
      float* __restrict__ C, int N, int K,
      const float* __restrict__ bias,
      const float* __restrict__ aux1, const float* __restrict__ aux2,
      const float* __restrict__ aux3,
      float* __restrict__ out2,
      __half* __restrict__ o_hi) {
    extern __shared__ char sm[];
    uint32_t sb = s2u(sm);
    int tid = threadIdx.x;
    int lane = tid & 31, wid = tid >> 5;
    int wm = wid >> 2, wn = wid & 3;          // warp tile 64x64 at (wm*64, wn*64)
    size_t mrow0 = (size_t)blockIdx.y * 128;
    size_t ncol0 = (size_t)blockIdx.x * 256;

    float acc[4][8][4];
    #pragma unroll
    for (int a = 0; a < 4; a++)
        #pragma unroll
        for (int b = 0; b < 8; b++)
            #pragma unroll
            for (int c = 0; c < 4; c++) acc[a][b][c] = 0.f;

    auto load_stage = [&](int s, int k0) {
        uint32_t base = sb + s * STG;
        // A: 128 rows x 64B
        #pragma unroll
        for (int i = 0; i < 2; i++) {
            int idx = tid + i * 256;
            int r = idx >> 2, c = idx & 3;
            uint32_t sw = r * 64 + ((c ^ ((r >> 1) & 3)) << 4);
            cpasync16(base + sw, Ah + (mrow0 + r) * K + k0 + c * 8);
        }
        // B: 256 rows x 64B
        #pragma unroll
        for (int i = 0; i < 4; i++) {
            int idx = tid + i * 256;
            int r = idx >> 2, c = idx & 3;
            uint32_t sw = r * 64 + ((c ^ ((r >> 1) & 3)) << 4);
            cpasync16(base + 8192 + sw, Bh + (ncol0 + r) * K + k0 + c * 8);
        }
    };

    const int KT = K >> 5;  // BK = 32
    load_stage(0, 0);
    cp_commit();
    load_stage(1, 32);
    cp_commit();

    for (int kt = 0; kt < KT; kt++) {
        if (kt + 1 < KT) cp_wait<1>(); else cp_wait<0>();
        __syncthreads();
        if (kt + 2 < KT) {
            int s = kt + 2;
            load_stage(s % 3, s << 5);
            cp_commit();
        }
        uint32_t base = sb + (kt % 3) * STG;
        #pragma unroll
        for (int kk = 0; kk < 2; kk++) {
            uint32_t ah[4][4], bh[4][4];
            int g = lane >> 3;
            int ar = (lane & 7) + ((g & 1) << 3);
            int ac = kk * 2 + (g >> 1);
            #pragma unroll
            for (int mi = 0; mi < 4; mi++) {
                int row = wm * 64 + mi * 16 + ar;
                uint32_t off = row * 64 + ((ac ^ ((row >> 1) & 3)) << 4);
                ldsm4(ah[mi], base + off);
            }
            int br = (lane & 7) + ((g >> 1) << 3);
            int bc = kk * 2 + (g & 1);
            #pragma unroll
            for (int ni = 0; ni < 4; ni++) {
                int row = wn * 64 + ni * 16 + br;
                uint32_t off = row * 64 + ((bc ^ ((row >> 1) & 3)) << 4);
                ldsm4(bh[ni], base + 8192 + off);
            }
            #pragma unroll
            for (int mi = 0; mi < 4; mi++)
                #pragma unroll
                for (int n8 = 0; n8 < 8; n8++)
                    mma16816(acc[mi][n8], ah[mi], &bh[n8 >> 1][(n8 & 1) * 2]);
        }
    }

    // ---------------- epilogue ----------------
    const float c0g = 0.7978845608028654f, c1g = 0.044715f;
    #pragma unroll
    for (int mi = 0; mi < 4; mi++) {
        #pragma unroll
        for (int n8 = 0; n8 < 8; n8++) {
            int col = (int)ncol0 + wn * 64 + n8 * 8 + (lane & 3) * 2;
            #pragma unroll
            for (int half_ = 0; half_ < 2; half_++) {
                size_t row = mrow0 + wm * 64 + mi * 16 + (lane >> 2) + half_ * 8;
                float v0 = acc[mi][n8][half_ * 2 + 0];
                float v1 = acc[mi][n8][half_ * 2 + 1];
                size_t off = row * N + col;
                if (EPI == 0) {
                    *(float2*)(C + off) = make_float2(v0, v1);
                } else if (EPI == 1) {
                    float2 bia = *(const float2*)(bias + col);
                    float2 lb  = *(const float2*)(aux3 + col);
                    float2 vel = *(const float2*)(aux1 + off);
                    float2 xv  = *(const float2*)(aux2 + off);
                    float vn0 = fmaf(1.f / (1.f + __expf(-lb.x)), vel.x, v0 + bia.x);
                    float vn1 = fmaf(1.f / (1.f + __expf(-lb.y)), vel.y, v1 + bia.y);
                    *(float2*)(C + off) = make_float2(vn0, vn1);
                    *(float2*)(out2 + off) = make_float2(xv.x + vn0, xv.y + vn1);
                } else if (EPI == 2) {
                    float2 bia = *(const float2*)(bias + col);
                    float t0 = v0 + bia.x, t1 = v1 + bia.y;
                    t0 = 0.5f * t0 * (1.f + tanhf(c0g * (t0 + c1g * t0 * t0 * t0)));
                    t1 = 0.5f * t1 * (1.f + tanhf(c0g * (t1 + c1g * t1 * t1 * t1)));
                    *(__half2*)(o_hi + off) =
                        __halves2half2(__float2half_rn(t0), __float2half_rn(t1));
                } else if (EPI == 3) {
                    float2 bia = *(const float2*)(bias + col);
                    float2 xn  = *(const float2*)(aux1 + off);
                    *(float2*)(C + off) = make_float2(v0 + bia.x + xn.x, v1 + bia.y + xn.y);
                } else {  // EPI == 4: gating. N==2048; 256-wide tile stays in one half.
                    if (col < 1024) {
                        float s0 = 1.f / (1.f + __expf(-v0));
                        float s1 = 1.f / (1.f + __expf(-v1));
                        *(__half2*)(o_hi + row * 1024 + col) =
                            __halves2half2(__float2half_rn(s0), __float2half_rn(s1));
                    } else {
                        int d = col - 1024;
                        float sp0 = aux3[d], sp1 = aux3[d + 1];
                        float sa0 = 1.f / (1.f + __expf(-v0));
                        float sa1 = 1.f / (1.f + __expf(-v1));
                        float a0 = expf(-sp0 * sa0);
                        float a1 = expf(-sp1 * sa1);
                        *(float2*)(C + row * 1024 + d) = make_float2(a0, a1);
                    }
                }
            }
        }
    }
}

// ---------------- launch ----------------
extern "C" void kernel_launch(void* const* d_in, const int* in_sizes, int n_in,
                              void* d_out, int out_size) {
    const float* x          = (const float*)d_in[0];
    const float* velocity   = (const float*)d_in[1];
    const float* pre_norm_w = (const float*)d_in[2];
    const float* conv_k     = (const float*)d_in[3];
    const float* conv_b     = (const float*)d_in[4];
    const float* W_gate     = (const float*)d_in[5];
    const float* W_a        = (const float*)d_in[6];
    const float* lam        = (const float*)d_in[7];
    const float* W_out      = (const float*)d_in[8];
    const float* b_out      = (const float*)d_in[9];
    const float* log_beta   = (const float*)d_in[10];
    const float* ffn_norm_w = (const float*)d_in[11];
    const float* W_ff1      = (const float*)d_in[12];
    const float* b_ff1      = (const float*)d_in[13];
    const float* W_ff2      = (const float*)d_in[14];
    const float* b_ff2      = (const float*)d_in[15];

    float* out1    = (float*)d_out;
    float* out_vel = out1 + BSD;

    __half *p_xn_h, *p_gate, *p_cc_h, *p_nm_h, *p_hd_h, *p_wt_h;
    float *p_a, *p_xnew, *p_splam;
    cudaGetSymbolAddress((void**)&p_xn_h, g_xn_h);
    cudaGetSymbolAddress((void**)&p_gate, g_gate);
    cudaGetSymbolAddress((void**)&p_a, g_a);
    cudaGetSymbolAddress((void**)&p_cc_h, g_cc_h);
    cudaGetSymbolAddress((void**)&p_nm_h, g_nm_h);
    cudaGetSymbolAddress((void**)&p_hd_h, g_hd_h);
    cudaGetSymbolAddress((void**)&p_wt_h, g_wt_h);
    cudaGetSymbolAddress((void**)&p_xnew, g_xnew);
    cudaGetSymbolAddress((void**)&p_splam, g_splam);

    cudaFuncSetAttribute(hgemm<1>, cudaFuncAttributeMaxDynamicSharedMemorySize, GEMM_SMEM);
    cudaFuncSetAttribute(hgemm<2>, cudaFuncAttributeMaxDynamicSharedMemorySize, GEMM_SMEM);
    cudaFuncSetAttribute(hgemm<3>, cudaFuncAttributeMaxDynamicSharedMemorySize, GEMM_SMEM);
    cudaFuncSetAttribute(hgemm<4>, cudaFuncAttributeMaxDynamicSharedMemorySize, GEMM_SMEM);

    // weight layout in g_wt_h (elements):
    //   [0,1M) gate  [1M,2M) a  [2M,4M) W_out^T  [4M,8M) W_ff1^T  [8M,12M) W_ff2^T
    const size_t OFF_GA = 0, OFF_OUT = (size_t)2 << 20,
                 OFF_FF1 = (size_t)4 << 20, OFF_FF2 = (size_t)8 << 20;
    transpose_all<<<12288, 256>>>(W_gate, W_a, W_out, W_ff1, W_ff2, p_wt_h);

    // pre-norm -> fp16
    rmsnorm_h<<<MM, 256>>>(x, pre_norm_w, p_xn_h);
    splam_kernel<<<4, 256>>>(lam);

    // fused gate+a GEMM (M=8192, N=2048, K=1024) with gating epilogue
    dim3 gGA(2048 / 256, MM / 128);
    hgemm<4><<<gGA, 256, GEMM_SMEM>>>(p_xn_h, p_wt_h + OFF_GA,
                                      p_a, 2048, 1024,
                                      nullptr, nullptr, nullptr, p_splam, nullptr, p_gate);

    // fused conv + u + scan chunk partials; combine; final scan
    gscan1_kernel<<<BB * DD * SCH / 256, 256>>>(conv_k, conv_b);
    scan_part2<<<BB * DD / 256, 256>>>();
    scan_part3<<<BB * DD * SCH / 256, 256>>>();

    // mixer GEMM (K=2048) + velocity + residual
    dim3 gD(1024 / 256, MM / 128);
    hgemm<1><<<gD, 256, GEMM_SMEM>>>(p_cc_h, p_wt_h + OFF_OUT,
                                     out_vel, 1024, 2048,
                                     b_out, velocity, x, log_beta, p_xnew, nullptr);

    // ffn norm
    rmsnorm_h<<<MM, 256>>>(p_xnew, ffn_norm_w, p_nm_h);

    // ff1 + gelu -> fp16 hidden (N=4096, K=1024)
    dim3 gF(4096 / 256, MM / 128);
    hgemm<2><<<gF, 256, GEMM_SMEM>>>(p_nm_h, p_wt_h + OFF_FF1,
                                     nullptr, 4096, 1024,
                                     b_ff1, nullptr, nullptr, nullptr, nullptr, p_hd_h);

    // ff2 + residual (K=4096) -> out1
    hgemm<3><<<gD, 256, GEMM_SMEM>>>(p_hd_h, p_wt_h + OFF_FF2,
                                     out1, 1024, 4096,
                                     b_ff2, p_xnew, nullptr, nullptr, nullptr, nullptr);
}

// round 9
// speedup vs baseline: 1.0361x; 1.0361x over previous
#include <cuda_runtime.h>
#include <cuda_fp16.h>
#include <math.h>
#include <stdint.h>

// ---------------- problem constants ----------------
constexpr int BB = 4, SSEQ = 2048, DD = 1024, FF = 4096;
constexpr int MM = BB * SSEQ;                 // 8192
constexpr long long BSD = (long long)MM * DD; // 8388608

// ---------------- scratch (device globals; no allocation) ----------------
__device__ __half g_xn_h[MM * DD];
__device__ __half g_gate[MM * DD];            // sigmoid(gate_pre), fp16
__device__ float  g_a[MM * DD];               // recurrence coefficient, fp32
__device__ __half g_u_h[MM * DD];             // scan input, fp16
__device__ __half g_cc_h[MM * 2 * DD];        // [conv | griffin_h] fp16
__device__ float  g_xnew[MM * DD];
__device__ __half g_nm_h[MM * DD];
__device__ __half g_hd_h[MM * FF];
__device__ __half g_wt_h[12 * 1024 * 1024];
__device__ float  g_splam[DD];
// chunked-scan partials
constexpr int SCH = 16, SLEN = SSEQ / SCH;
__device__ float g_P[BB * DD * SCH], g_Hp[BB * DD * SCH], g_Cc[BB * DD * SCH];

// ---------------- helpers ----------------
__device__ __forceinline__ uint32_t s2u(const void* p) {
    uint32_t a;
    asm("{ .reg .u64 t; cvta.to.shared.u64 t, %1; cvt.u32.u64 %0, t; }" : "=r"(a) : "l"(p));
    return a;
}
__device__ __forceinline__ void cpasync16(uint32_t saddr, const void* g) {
    asm volatile("cp.async.cg.shared.global [%0], [%1], 16;" :: "r"(saddr), "l"(g));
}
__device__ __forceinline__ void cp_commit() {
    asm volatile("cp.async.commit_group;" ::: "memory");
}
template <int N>
__device__ __forceinline__ void cp_wait() {
    asm volatile("cp.async.wait_group %0;" :: "n"(N) : "memory");
}
__device__ __forceinline__ void ldsm4(uint32_t* r, uint32_t addr) {
    asm volatile("ldmatrix.sync.aligned.m8n8.x4.shared.b16 {%0,%1,%2,%3}, [%4];"
                 : "=r"(r[0]), "=r"(r[1]), "=r"(r[2]), "=r"(r[3]) : "r"(addr));
}
__device__ __forceinline__ void mma16816(float* d, const uint32_t* a, const uint32_t* b) {
    asm volatile(
        "mma.sync.aligned.m16n8k16.row.col.f32.f16.f16.f32 "
        "{%0,%1,%2,%3}, {%4,%5,%6,%7}, {%8,%9}, {%0,%1,%2,%3};"
        : "+f"(d[0]), "+f"(d[1]), "+f"(d[2]), "+f"(d[3])
        : "r"(a[0]), "r"(a[1]), "r"(a[2]), "r"(a[3]), "r"(b[0]), "r"(b[1]));
}

// ------- merged weight transpose: all 5 weights, one launch -------
__global__ void transpose_all(const float* __restrict__ Wg, const float* __restrict__ Wa,
                              const float* __restrict__ Wo, const float* __restrict__ W1,
                              const float* __restrict__ W2, __half* __restrict__ out) {
    int b = blockIdx.x;
    const float* W;
    int K, N;
    size_t off;
    int tile;
    if (b < 1024)      { W = Wg; K = 1024; N = 1024; off = 0;               tile = b; }
    else if (b < 2048) { W = Wa; K = 1024; N = 1024; off = (size_t)1 << 20; tile = b - 1024; }
    else if (b < 4096) { W = Wo; K = 2048; N = 1024; off = (size_t)2 << 20; tile = b - 2048; }
    else if (b < 8192) { W = W1; K = 1024; N = 4096; off = (size_t)4 << 20; tile = b - 4096; }
    else               { W = W2; K = 4096; N = 1024; off = (size_t)8 << 20; tile = b - 8192; }
    int ntn = N >> 5;
    int n0 = (tile % ntn) * 32, k0 = (tile / ntn) * 32;
    __half* oh = out + off;

    __shared__ float t[32][33];
    int tid = threadIdx.x;
    #pragma unroll
    for (int i = 0; i < 4; i++) {
        int idx = tid + i * 256;
        int kr = idx >> 5, nc = idx & 31;
        t[kr][nc] = W[(size_t)(k0 + kr) * N + n0 + nc];
    }
    __syncthreads();
    #pragma unroll
    for (int i = 0; i < 2; i++) {
        int idx = tid + i * 256;
        int nr = idx >> 4, kp = idx & 15;
        float v0 = t[kp * 2][nr], v1 = t[kp * 2 + 1][nr];
        size_t o = (size_t)(n0 + nr) * K + k0 + kp * 2;
        *(__half2*)(oh + o) = __halves2half2(__float2half_rn(v0), __float2half_rn(v1));
    }
}

// ---------------- rmsnorm -> fp16 ----------------
__global__ void rmsnorm_h(const float* __restrict__ in, const float* __restrict__ w,
                          __half* __restrict__ oh) {
    int row = blockIdx.x;
    const float4* ip = (const float4*)(in + (size_t)row * DD);
    float4 v = ip[threadIdx.x];
    float ss = v.x * v.x + v.y * v.y + v.z * v.z + v.w * v.w;
    #pragma unroll
    for (int o = 16; o > 0; o >>= 1) ss += __shfl_xor_sync(0xffffffffu, ss, o);
    __shared__ float ws[8];
    int lane = threadIdx.x & 31, wid = threadIdx.x >> 5;
    if (lane == 0) ws[wid] = ss;
    __syncthreads();
    if (wid == 0) {
        float s = (lane < 8) ? ws[lane] : 0.f;
        #pragma unroll
        for (int o = 4; o > 0; o >>= 1) s += __shfl_xor_sync(0xffffffffu, s, o);
        if (lane == 0) ws[0] = s;
    }
    __syncthreads();
    float rms = rsqrtf(ws[0] * (1.0f / DD) + 1e-6f);
    float4 wv = ((const float4*)w)[threadIdx.x];
    size_t o0 = (size_t)row * DD + threadIdx.x * 4;
    *(__half2*)(oh + o0)     = __halves2half2(__float2half_rn(v.x * rms * wv.x),
                                              __float2half_rn(v.y * rms * wv.y));
    *(__half2*)(oh + o0 + 2) = __halves2half2(__float2half_rn(v.z * rms * wv.z),
                                              __float2half_rn(v.w * rms * wv.w));
}

// ---------------- splam[d] = 8 * softplus(lam[d]) ----------------
__global__ void splam_kernel(const float* __restrict__ lam) {
    int d = blockIdx.x * blockDim.x + threadIdx.x;
    if (d < DD) {
        float l = lam[d];
        float sp = (l > 20.f) ? l : log1pf(expf(l));
        g_splam[d] = 8.0f * sp;
    }
}

// ------- fused: conv + u + scan chunk-partials (thread = b,ch,d) -------
__global__ void gscan1_kernel(const float* __restrict__ ck, const float* __restrict__ cb) {
    int gid = blockIdx.x * 256 + threadIdx.x;      // (b*SCH + ch)*DD + d
    int d = gid & (DD - 1);
    int ch = (gid >> 10) & (SCH - 1);
    int b = gid >> 14;
    float4 kv = ((const float4*)ck)[d];
    float cbias = cb[d];

    long long r0 = (long long)b * SSEQ + ch * SLEN;
    long long xbase = r0 * DD + d;
    float xm1 = 0.f, xm2 = 0.f, xm3 = 0.f;
    if (ch > 0) {
        xm1 = __half2float(g_xn_h[xbase - DD]);
        xm2 = __half2float(g_xn_h[xbase - 2 * DD]);
        xm3 = __half2float(g_xn_h[xbase - 3 * DD]);
    }
    float p = 1.f, h = 0.f;
    #pragma unroll 4
    for (int t = 0; t < SLEN; t++) {
        long long i = xbase + (long long)t * DD;
        long long r = r0 + t;
        float xn = __half2float(g_xn_h[i]);
        float conv = cbias + kv.x * xn + kv.y * xm1 + kv.z * xm2 + kv.w * xm3;
        float gate = __half2float(g_gate[i]);
        float a = g_a[i];
        float u = sqrtf(fmaxf(1.f - a * a, 0.f)) * gate * xn;
        g_cc_h[r * (2 * DD) + d] = __float2half_rn(conv);
        g_u_h[i] = __float2half_rn(u);
        p *= a;
        h = fmaf(a, h, u);
        xm3 = xm2; xm2 = xm1; xm1 = xn;
    }
    g_P[gid] = p;
    g_Hp[gid] = h;
}

__global__ void scan_part2() {
    int c = blockIdx.x * 256 + threadIdx.x;
    int b = c >> 10, d = c & (DD - 1);
    float carry = 0.f;
    #pragma unroll
    for (int ch = 0; ch < SCH; ch++) {
        int i = (b * SCH + ch) * DD + d;
        g_Cc[i] = carry;
        carry = fmaf(g_P[i], carry, g_Hp[i]);
    }
}
__global__ void scan_part3() {
    int gid = blockIdx.x * 256 + threadIdx.x;
    int d = gid & (DD - 1);
    int ch = (gid >> 10) & (SCH - 1);
    int b = gid >> 14;
    long long base = ((long long)b * SSEQ + ch * SLEN) * DD + d;
    float h = g_Cc[gid];
    #pragma unroll 4
    for (int t = 0; t < SLEN; t++) {
        long long idx = base + (long long)t * DD;
        h = fmaf(g_a[idx], h, __half2float(g_u_h[idx]));
        long long row = (long long)b * SSEQ + ch * SLEN + t;
        g_cc_h[row * (2 * DD) + DD + d] = __float2half_rn(h);
    }
}

// ------- HMMA GEMM: 128x128 CTA tile, 4 warps, 64x64 warp tiles, BK=32 -------
// 3-stage cp.async, 2 CTAs/SM. grid: x = N-blocks, y = M-blocks.
// EPI: 0 plain fp32; 1 mixer; 2 gelu->fp16; 3 +bias+aux residual;
//      4 gating (gate->fp16 o_hi, a=exp(-splam*sigmoid)->fp32 C, N-stride 1024)
constexpr int STG = 16384;           // A 8K | B 8K
constexpr int GEMM_SMEM = 3 * STG;   // 48 KB

template <int EPI>
__global__ void __launch_bounds__(128, 2)
hgemm(const __half* __restrict__ Ah, const __half* __restrict__ Bh,
      float* __restrict__ C, int N, int K,
      const float* __restrict__ bias,
      const float* __restrict__ aux1, const float* __restrict__ aux2,
      const float* __restrict__ aux3,
      float* __restrict__ out2,
      __half* __restrict__ o_hi) {
    extern __shared__ char sm[];
    uint32_t sb = s2u(sm);
    int tid = threadIdx.x;
    int lane = tid & 31, wid = tid >> 5;
    int wm = wid >> 1, wn = wid & 1;          // warp tile 64x64 at (wm*64, wn*64)
    size_t mrow0 = (size_t)blockIdx.y * 128;
    size_t ncol0 = (size_t)blockIdx.x * 128;

    float acc[4][8][4];
    #pragma unroll
    for (int a = 0; a < 4; a++)
        #pragma unroll
        for (int b = 0; b < 8; b++)
            #pragma unroll
            for (int c = 0; c < 4; c++) acc[a][b][c] = 0.f;

    auto load_stage = [&](int s, int k0) {
        uint32_t base = sb + s * STG;
        // A then B: each 128 rows x 64B = 512 chunks; 128 threads x 4 iters
        #pragma unroll
        for (int i = 0; i < 4; i++) {
            int idx = tid + i * 128;
            int r = idx >> 2, c = idx & 3;
            uint32_t sw = r * 64 + ((c ^ ((r >> 1) & 3)) << 4);
            cpasync16(base + sw, Ah + (mrow0 + r) * K + k0 + c * 8);
            cpasync16(base + 8192 + sw, Bh + (ncol0 + r) * K + k0 + c * 8);
        }
    };

    const int KT = K >> 5;  // BK = 32
    load_stage(0, 0);
    cp_commit();
    load_stage(1, 32);
    cp_commit();

    for (int kt = 0; kt < KT; kt++) {
        if (kt + 1 < KT) cp_wait<1>(); else cp_wait<0>();
        __syncthreads();
        if (kt + 2 < KT) {
            int s = kt + 2;
            load_stage(s % 3, s << 5);
            cp_commit();
        }
        uint32_t base = sb + (kt % 3) * STG;
        #pragma unroll
        for (int kk = 0; kk < 2; kk++) {
            uint32_t ah[4][4], bh[4][4];
            int g = lane >> 3;
            int ar = (lane & 7) + ((g & 1) << 3);
            int ac = kk * 2 + (g >> 1);
            #pragma unroll
            for (int mi = 0; mi < 4; mi++) {
                int row = wm * 64 + mi * 16 + ar;
                uint32_t off = row * 64 + ((ac ^ ((row >> 1) & 3)) << 4);
                ldsm4(ah[mi], base + off);
            }
            int br = (lane & 7) + ((g >> 1) << 3);
            int bc = kk * 2 + (g & 1);
            #pragma unroll
            for (int ni = 0; ni < 4; ni++) {
                int row = wn * 64 + ni * 16 + br;
                uint32_t off = row * 64 + ((bc ^ ((row >> 1) & 3)) << 4);
                ldsm4(bh[ni], base + 8192 + off);
            }
            #pragma unroll
            for (int mi = 0; mi < 4; mi++)
                #pragma unroll
                for (int n8 = 0; n8 < 8; n8++)
                    mma16816(acc[mi][n8], ah[mi], &bh[n8 >> 1][(n8 & 1) * 2]);
        }
    }

    // ---------------- epilogue ----------------
    const float c0g = 0.7978845608028654f, c1g = 0.044715f;
    #pragma unroll
    for (int mi = 0; mi < 4; mi++) {
        #pragma unroll
        for (int n8 = 0; n8 < 8; n8++) {
            int col = (int)ncol0 + wn * 64 + n8 * 8 + (lane & 3) * 2;
            #pragma unroll
            for (int half_ = 0; half_ < 2; half_++) {
                size_t row = mrow0 + wm * 64 + mi * 16 + (lane >> 2) + half_ * 8;
                float v0 = acc[mi][n8][half_ * 2 + 0];
                float v1 = acc[mi][n8][half_ * 2 + 1];
                size_t off = row * N + col;
                if (EPI == 0) {
                    *(float2*)(C + off) = make_float2(v0, v1);
                } else if (EPI == 1) {
                    float2 bia = *(const float2*)(bias + col);
                    float2 lb  = *(const float2*)(aux3 + col);
                    float2 vel = *(const float2*)(aux1 + off);
                    float2 xv  = *(const float2*)(aux2 + off);
                    float vn0 = fmaf(1.f / (1.f + __expf(-lb.x)), vel.x, v0 + bia.x);
                    float vn1 = fmaf(1.f / (1.f + __expf(-lb.y)), vel.y, v1 + bia.y);
                    *(float2*)(C + off) = make_float2(vn0, vn1);
                    *(float2*)(out2 + off) = make_float2(xv.x + vn0, xv.y + vn1);
                } else if (EPI == 2) {
                    float2 bia = *(const float2*)(bias + col);
                    float t0 = v0 + bia.x, t1 = v1 + bia.y;
                    t0 = 0.5f * t0 * (1.f + tanhf(c0g * (t0 + c1g * t0 * t0 * t0)));
                    t1 = 0.5f * t1 * (1.f + tanhf(c0g * (t1 + c1g * t1 * t1 * t1)));
                    *(__half2*)(o_hi + off) =
                        __halves2half2(__float2half_rn(t0), __float2half_rn(t1));
                } else if (EPI == 3) {
                    float2 bia = *(const float2*)(bias + col);
                    float2 xn  = *(const float2*)(aux1 + off);
                    *(float2*)(C + off) = make_float2(v0 + bia.x + xn.x, v1 + bia.y + xn.y);
                } else {  // EPI == 4: gating. N==2048; tile is entirely in one half.
                    if (col < 1024) {
                        float s0 = 1.f / (1.f + __expf(-v0));
                        float s1 = 1.f / (1.f + __expf(-v1));
                        *(__half2*)(o_hi + row * 1024 + col) =
                            __halves2half2(__float2half_rn(s0), __float2half_rn(s1));
                    } else {
                        int d = col - 1024;
                        float sp0 = aux3[d], sp1 = aux3[d + 1];
                        float sa0 = 1.f / (1.f + __expf(-v0));
                        float sa1 = 1.f / (1.f + __expf(-v1));
                        float a0 = expf(-sp0 * sa0);
                        float a1 = expf(-sp1 * sa1);
                        *(float2*)(C + row * 1024 + d) = make_float2(a0, a1);
                    }
                }
            }
        }
    }
}

// ---------------- launch ----------------
extern "C" void kernel_launch(void* const* d_in, const int* in_sizes, int n_in,
                              void* d_out, int out_size) {
    const float* x          = (const float*)d_in[0];
    const float* velocity   = (const float*)d_in[1];
    const float* pre_norm_w = (const float*)d_in[2];
    const float* conv_k     = (const float*)d_in[3];
    const float* conv_b     = (const float*)d_in[4];
    const float* W_gate     = (const float*)d_in[5];
    const float* W_a        = (const float*)d_in[6];
    const float* lam        = (const float*)d_in[7];
    const float* W_out      = (const float*)d_in[8];
    const float* b_out      = (const float*)d_in[9];
    const float* log_beta   = (const float*)d_in[10];
    const float* ffn_norm_w = (const float*)d_in[11];
    const float* W_ff1      = (const float*)d_in[12];
    const float* b_ff1      = (const float*)d_in[13];
    const float* W_ff2      = (const float*)d_in[14];
    const float* b_ff2      = (const float*)d_in[15];

    float* out1    = (float*)d_out;
    float* out_vel = out1 + BSD;

    __half *p_xn_h, *p_gate, *p_cc_h, *p_nm_h, *p_hd_h, *p_wt_h;
    float *p_a, *p_xnew, *p_splam;
    cudaGetSymbolAddress((void**)&p_xn_h, g_xn_h);
    cudaGetSymbolAddress((void**)&p_gate, g_gate);
    cudaGetSymbolAddress((void**)&p_a, g_a);
    cudaGetSymbolAddress((void**)&p_cc_h, g_cc_h);
    cudaGetSymbolAddress((void**)&p_nm_h, g_nm_h);
    cudaGetSymbolAddress((void**)&p_hd_h, g_hd_h);
    cudaGetSymbolAddress((void**)&p_wt_h, g_wt_h);
    cudaGetSymbolAddress((void**)&p_xnew, g_xnew);
    cudaGetSymbolAddress((void**)&p_splam, g_splam);

    cudaFuncSetAttribute(hgemm<1>, cudaFuncAttributeMaxDynamicSharedMemorySize, GEMM_SMEM);
    cudaFuncSetAttribute(hgemm<2>, cudaFuncAttributeMaxDynamicSharedMemorySize, GEMM_SMEM);
    cudaFuncSetAttribute(hgemm<3>, cudaFuncAttributeMaxDynamicSharedMemorySize, GEMM_SMEM);
    cudaFuncSetAttribute(hgemm<4>, cudaFuncAttributeMaxDynamicSharedMemorySize, GEMM_SMEM);

    // weight layout in g_wt_h (elements):
    //   [0,1M) gate  [1M,2M) a  [2M,4M) W_out^T  [4M,8M) W_ff1^T  [8M,12M) W_ff2^T
    const size_t OFF_GA = 0, OFF_OUT = (size_t)2 << 20,
                 OFF_FF1 = (size_t)4 << 20, OFF_FF2 = (size_t)8 << 20;
    transpose_all<<<12288, 256>>>(W_gate, W_a, W_out, W_ff1, W_ff2, p_wt_h);

    // pre-norm -> fp16
    rmsnorm_h<<<MM, 256>>>(x, pre_norm_w, p_xn_h);
    splam_kernel<<<4, 256>>>(lam);

    // fused gate+a GEMM (M=8192, N=2048, K=1024) with gating epilogue
    dim3 gGA(2048 / 128, MM / 128);
    hgemm<4><<<gGA, 128, GEMM_SMEM>>>(p_xn_h, p_wt_h + OFF_GA,
                                      p_a, 2048, 1024,
                                      nullptr, nullptr, nullptr, p_splam, nullptr, p_gate);

    // fused conv + u + scan chunk partials; combine; final scan
    gscan1_kernel<<<BB * DD * SCH / 256, 256>>>(conv_k, conv_b);
    scan_part2<<<BB * DD / 256, 256>>>();
    scan_part3<<<BB * DD * SCH / 256, 256>>>();

    // mixer GEMM (K=2048) + velocity + residual
    dim3 gD(1024 / 128, MM / 128);
    hgemm<1><<<gD, 128, GEMM_SMEM>>>(p_cc_h, p_wt_h + OFF_OUT,
                                     out_vel, 1024, 2048,
                                     b_out, velocity, x, log_beta, p_xnew, nullptr);

    // ffn norm
    rmsnorm_h<<<MM, 256>>>(p_xnew, ffn_norm_w, p_nm_h);

    // ff1 + gelu -> fp16 hidden (N=4096, K=1024)
    dim3 gF(4096 / 128, MM / 128);
    hgemm<2><<<gF, 128, GEMM_SMEM>>>(p_nm_h, p_wt_h + OFF_FF1,
                                     nullptr, 4096, 1024,
                                     b_ff1, nullptr, nullptr, nullptr, nullptr, p_hd_h);

    // ff2 + residual (K=4096) -> out1
    hgemm<3><<<gD, 128, GEMM_SMEM>>>(p_hd_h, p_wt_h + OFF_FF2,
                                     out1, 1024, 4096,
                                     b_ff2, p_xnew, nullptr, nullptr, nullptr, nullptr);
}

// round 10
// speedup vs baseline: 1.1112x; 1.0725x over previous
#include <cuda_runtime.h>
#include <cuda_fp16.h>
#include <math.h>
#include <stdint.h>

// ---------------- problem constants ----------------
constexpr int BB = 4, SSEQ = 2048, DD = 1024, FF = 4096;
constexpr int MM = BB * SSEQ;                 // 8192
constexpr long long BSD = (long long)MM * DD; // 8388608

// ---------------- scratch (device globals; no allocation) ----------------
__device__ __half g_xn_h[MM * DD];
__device__ __half g_gate[MM * DD];            // sigmoid(gate_pre), fp16
__device__ float  g_a[MM * DD];               // recurrence coefficient, fp32
__device__ __half g_cc_h[MM * 2 * DD];        // [conv | griffin_h] fp16
__device__ float  g_xnew[MM * DD];
__device__ __half g_nm_h[MM * DD];
__device__ __half g_hd_h[MM * FF];
__device__ __half g_wt_h[12 * 1024 * 1024];
__device__ float  g_splam[DD];
// decoupled-lookback scan records: 32 chunks x (B*D) channels
constexpr int SCH = 32, SLEN = SSEQ / SCH;    // 32 chunks of 64
__device__ float2 g_recPH[BB * SCH * DD];     // (p, h) partial
__device__ float  g_recI [BB * SCH * DD];     // inclusive H

// ---------------- helpers ----------------
__device__ __forceinline__ uint32_t s2u(const void* p) {
    uint32_t a;
    asm("{ .reg .u64 t; cvta.to.shared.u64 t, %1; cvt.u32.u64 %0, t; }" : "=r"(a) : "l"(p));
    return a;
}
__device__ __forceinline__ void cpasync16(uint32_t saddr, const void* g) {
    asm volatile("cp.async.cg.shared.global [%0], [%1], 16;" :: "r"(saddr), "l"(g));
}
__device__ __forceinline__ void cp_commit() {
    asm volatile("cp.async.commit_group;" ::: "memory");
}
template <int N>
__device__ __forceinline__ void cp_wait() {
    asm volatile("cp.async.wait_group %0;" :: "n"(N) : "memory");
}
__device__ __forceinline__ void ldsm4(uint32_t* r, uint32_t addr) {
    asm volatile("ldmatrix.sync.aligned.m8n8.x4.shared.b16 {%0,%1,%2,%3}, [%4];"
                 : "=r"(r[0]), "=r"(r[1]), "=r"(r[2]), "=r"(r[3]) : "r"(addr));
}
__device__ __forceinline__ void mma16816(float* d, const uint32_t* a, const uint32_t* b) {
    asm volatile(
        "mma.sync.aligned.m16n8k16.row.col.f32.f16.f16.f32 "
        "{%0,%1,%2,%3}, {%4,%5,%6,%7}, {%8,%9}, {%0,%1,%2,%3};"
        : "+f"(d[0]), "+f"(d[1]), "+f"(d[2]), "+f"(d[3])
        : "r"(a[0]), "r"(a[1]), "r"(a[2]), "r"(a[3]), "r"(b[0]), "r"(b[1]));
}
// L2-level (device-visible) 8B/4B load/store for lookback protocol
__device__ __forceinline__ float2 ldcg2(const float2* p) {
    float2 v;
    asm volatile("ld.global.cg.v2.f32 {%0,%1}, [%2];" : "=f"(v.x), "=f"(v.y) : "l"(p));
    return v;
}
__device__ __forceinline__ void stcg2(float2* p, float2 v) {
    asm volatile("st.global.cg.v2.f32 [%0], {%1,%2};" :: "l"(p), "f"(v.x), "f"(v.y) : "memory");
}
__device__ __forceinline__ float ldcg1(const float* p) {
    float v;
    asm volatile("ld.global.cg.f32 %0, [%1];" : "=f"(v) : "l"(p));
    return v;
}
__device__ __forceinline__ void stcg1(float* p, float v) {
    asm volatile("st.global.cg.f32 [%0], %1;" :: "l"(p), "f"(v) : "memory");
}

// ------- merged weight transpose: all 5 weights, one launch -------
__global__ void transpose_all(const float* __restrict__ Wg, const float* __restrict__ Wa,
                              const float* __restrict__ Wo, const float* __restrict__ W1,
                              const float* __restrict__ W2, __half* __restrict__ out) {
    int b = blockIdx.x;
    const float* W;
    int K, N;
    size_t off;
    int tile;
    if (b < 1024)      { W = Wg; K = 1024; N = 1024; off = 0;               tile = b; }
    else if (b < 2048) { W = Wa; K = 1024; N = 1024; off = (size_t)1 << 20; tile = b - 1024; }
    else if (b < 4096) { W = Wo; K = 2048; N = 1024; off = (size_t)2 << 20; tile = b - 2048; }
    else if (b < 8192) { W = W1; K = 1024; N = 4096; off = (size_t)4 << 20; tile = b - 4096; }
    else               { W = W2; K = 4096; N = 1024; off = (size_t)8 << 20; tile = b - 8192; }
    int ntn = N >> 5;
    int n0 = (tile % ntn) * 32, k0 = (tile / ntn) * 32;
    __half* oh = out + off;

    __shared__ float t[32][33];
    int tid = threadIdx.x;
    #pragma unroll
    for (int i = 0; i < 4; i++) {
        int idx = tid + i * 256;
        int kr = idx >> 5, nc = idx & 31;
        t[kr][nc] = W[(size_t)(k0 + kr) * N + n0 + nc];
    }
    __syncthreads();
    #pragma unroll
    for (int i = 0; i < 2; i++) {
        int idx = tid + i * 256;
        int nr = idx >> 4, kp = idx & 15;
        float v0 = t[kp * 2][nr], v1 = t[kp * 2 + 1][nr];
        size_t o = (size_t)(n0 + nr) * K + k0 + kp * 2;
        *(__half2*)(oh + o) = __halves2half2(__float2half_rn(v0), __float2half_rn(v1));
    }
}

// ---------------- rmsnorm -> fp16 ----------------
__global__ void rmsnorm_h(const float* __restrict__ in, const float* __restrict__ w,
                          __half* __restrict__ oh) {
    int row = blockIdx.x;
    const float4* ip = (const float4*)(in + (size_t)row * DD);
    float4 v = ip[threadIdx.x];
    float ss = v.x * v.x + v.y * v.y + v.z * v.z + v.w * v.w;
    #pragma unroll
    for (int o = 16; o > 0; o >>= 1) ss += __shfl_xor_sync(0xffffffffu, ss, o);
    __shared__ float ws[8];
    int lane = threadIdx.x & 31, wid = threadIdx.x >> 5;
    if (lane == 0) ws[wid] = ss;
    __syncthreads();
    if (wid == 0) {
        float s = (lane < 8) ? ws[lane] : 0.f;
        #pragma unroll
        for (int o = 4; o > 0; o >>= 1) s += __shfl_xor_sync(0xffffffffu, s, o);
        if (lane == 0) ws[0] = s;
    }
    __syncthreads();
    float rms = rsqrtf(ws[0] * (1.0f / DD) + 1e-6f);
    float4 wv = ((const float4*)w)[threadIdx.x];
    size_t o0 = (size_t)row * DD + threadIdx.x * 4;
    *(__half2*)(oh + o0)     = __halves2half2(__float2half_rn(v.x * rms * wv.x),
                                              __float2half_rn(v.y * rms * wv.y));
    *(__half2*)(oh + o0 + 2) = __halves2half2(__float2half_rn(v.z * rms * wv.z),
                                              __float2half_rn(v.w * rms * wv.w));
}

// ---------------- splam[d] = 8 * softplus(lam[d]) ----------------
__global__ void splam_kernel(const float* __restrict__ lam) {
    int d = blockIdx.x * blockDim.x + threadIdx.x;
    if (d < DD) {
        float l = lam[d];
        float sp = (l > 20.f) ? l : log1pf(expf(l));
        g_splam[d] = 8.0f * sp;
    }
}

// ------- clear lookback records to NaN sentinel (fresh each launch) -------
__global__ void clear_rec() {
    int i = blockIdx.x * 256 + threadIdx.x;   // < BB*SCH*DD = 131072
    float nf = __int_as_float(0x7fffffff);
    g_recPH[i] = make_float2(nf, nf);
    g_recI[i] = nf;
}

// ------- single-pass scan: conv + u + chunk scan + decoupled lookback -------
// block = (ch, b, dblk); thread owns one d; chunk (a,u) staged in smem (128 KB).
// Predecessor chunks have LOWER blockIdx (forward-progress per CUB model).
__global__ void __launch_bounds__(256) gscan_one(const float* __restrict__ ck,
                                                 const float* __restrict__ cb) {
    extern __shared__ float2 au[];            // [SLEN][256]
    int tid = threadIdx.x;
    int bid = blockIdx.x;                     // ch*16 + b*4 + dblk
    int ch = bid >> 4;
    int b = (bid >> 2) & 3;
    int dblk = bid & 3;
    int d = dblk * 256 + tid;

    float4 kv = ((const float4*)ck)[d];
    float cbias = cb[d];

    long long r0 = (long long)b * SSEQ + ch * SLEN;
    long long xbase = r0 * DD + d;
    float xm1 = 0.f, xm2 = 0.f, xm3 = 0.f;
    if (ch > 0) {
        xm1 = __half2float(g_xn_h[xbase - DD]);
        xm2 = __half2float(g_xn_h[xbase - 2 * DD]);
        xm3 = __half2float(g_xn_h[xbase - 3 * DD]);
    }
    float p = 1.f, h = 0.f;
    #pragma unroll 4
    for (int t = 0; t < SLEN; t++) {
        long long i = xbase + (long long)t * DD;
        float xn = __half2float(g_xn_h[i]);
        float conv = cbias + kv.x * xn + kv.y * xm1 + kv.z * xm2 + kv.w * xm3;
        float gate = __half2float(g_gate[i]);
        float a = g_a[i];
        float u = sqrtf(fmaxf(1.f - a * a, 0.f)) * gate * xn;
        g_cc_h[(r0 + t) * (2 * DD) + d] = __float2half_rn(conv);
        au[t * 256 + tid] = make_float2(a, u);
        p *= a;
        h = fmaf(a, h, u);
        xm3 = xm2; xm2 = xm1; xm1 = xn;
    }

    int recbase = b * SCH * DD + d;           // + ch*DD per chunk
    stcg2(&g_recPH[recbase + ch * DD], make_float2(p, h));   // publish partial (8B atomic)

    // decoupled lookback: resolve carry C = inclusive H of chunk ch-1
    float C = 0.f;
    if (ch > 0) {
        float accP = 1.f, accH = 0.f;
        int look = ch - 1;
        while (true) {
            float hi = ldcg1(&g_recI[recbase + look * DD]);
            if (!isnan(hi)) { C = fmaf(accP, hi, accH); break; }
            float2 ph = ldcg2(&g_recPH[recbase + look * DD]);
            if (!isnan(ph.x)) {
                accH = fmaf(accP, ph.y, accH);
                accP *= ph.x;
                if (--look < 0) { C = accH; break; }
            }
        }
    }
    stcg1(&g_recI[recbase + ch * DD], fmaf(p, C, h));        // publish inclusive

    // phase 2: replay chunk from smem with carry
    h = C;
    #pragma unroll 4
    for (int t = 0; t < SLEN; t++) {
        float2 v = au[t * 256 + tid];
        h = fmaf(v.x, h, v.y);
        g_cc_h[(r0 + t) * (2 * DD) + DD + d] = __float2half_rn(h);
    }
}

// ------- HMMA GEMM (R7 config): 128x128 tile, 8 warps, 64x32 warp tiles -------
// BK=32, 3-stage cp.async, 2 CTAs/SM. grid: x = N-blocks, y = M-blocks.
// EPI: 0 plain fp32; 1 mixer; 2 gelu->fp16; 3 +bias+aux residual;
//      4 gating (gate->fp16 o_hi, a=exp(-splam*sigmoid)->fp32 C, N-stride 1024)
constexpr int STG = 16384;           // A 8K | B 8K
constexpr int GEMM_SMEM = 3 * STG;   // 48 KB

template <int EPI>
__global__ void __launch_bounds__(256)
hgemm(const __half* __restrict__ Ah, const __half* __restrict__ Bh,
      float* __restrict__ C, int N, int K,
      const float* __restrict__ bias,
      const float* __restrict__ aux1, const float* __restrict__ aux2,
      const float* __restrict__ aux3,
      float* __restrict__ out2,
      __half* __restrict__ o_hi) {
    extern __shared__ char sm[];
    uint32_t sb = s2u(sm);
    int tid = threadIdx.x;
    int lane = tid & 31, wid = tid >> 5;
    int wm = wid >> 2, wn = wid & 3;          // warp tile 64x32 at (wm*64, wn*32)
    size_t mrow0 = (size_t)blockIdx.y * 128;
    size_t ncol0 = (size_t)blockIdx.x * 128;

    float acc[4][4][4];
    #pragma unroll
    for (int a = 0; a < 4; a++)
        #pragma unroll
        for (int b = 0; b < 4; b++)
            #pragma unroll
            for (int c = 0; c < 4; c++) acc[a][b][c] = 0.f;

    auto load_stage = [&](int s, int k0) {
        uint32_t base = sb + s * STG;
        #pragma unroll
        for (int i = 0; i < 2; i++) {
            int idx = tid + i * 256;
            int r = idx >> 2, c = idx & 3;
            uint32_t sw = r * 64 + ((c ^ ((r >> 1) & 3)) << 4);
            cpasync16(base + sw, Ah + (mrow0 + r) * K + k0 + c * 8);
            cpasync16(base + 8192 + sw, Bh + (ncol0 + r) * K + k0 + c * 8);
        }
    };

    const int KT = K >> 5;  // BK = 32
    load_stage(0, 0);
    cp_commit();
    load_stage(1, 32);
    cp_commit();

    for (int kt = 0; kt < KT; kt++) {
        if (kt + 1 < KT) cp_wait<1>(); else cp_wait<0>();
        __syncthreads();
        if (kt + 2 < KT) {
            int s = kt + 2;
            load_stage(s % 3, s << 5);
            cp_commit();
        }
        uint32_t base = sb + (kt % 3) * STG;
        #pragma unroll
        for (int kk = 0; kk < 2; kk++) {
            uint32_t ah[4][4], bh[2][4];
            int g = lane >> 3;
            int ar = (lane & 7) + ((g & 1) << 3);
            int ac = kk * 2 + (g >> 1);
            #pragma unroll
            for (int mi = 0; mi < 4; mi++) {
                int row = wm * 64 + mi * 16 + ar;
                uint32_t off = row * 64 + ((ac ^ ((row >> 1) & 3)) << 4);
                ldsm4(ah[mi], base + off);
            }
            int br = (lane & 7) + ((g >> 1) << 3);
            int bc = kk * 2 + (g & 1);
            #pragma unroll
            for (int ni = 0; ni < 2; ni++) {
                int row = wn * 32 + ni * 16 + br;
                uint32_t off = row * 64 + ((bc ^ ((row >> 1) & 3)) << 4);
                ldsm4(bh[ni], base + 8192 + off);
            }
            #pragma unroll
            for (int mi = 0; mi < 4; mi++)
                #pragma unroll
                for (int n8 = 0; n8 < 4; n8++)
                    mma16816(acc[mi][n8], ah[mi], &bh[n8 >> 1][(n8 & 1) * 2]);
        }
    }

    // ---------------- epilogue ----------------
    const float c0g = 0.7978845608028654f, c1g = 0.044715f;
    #pragma unroll
    for (int mi = 0; mi < 4; mi++) {
        #pragma unroll
        for (int n8 = 0; n8 < 4; n8++) {
            int col = (int)ncol0 + wn * 32 + n8 * 8 + (lane & 3) * 2;
            #pragma unroll
            for (int half_ = 0; half_ < 2; half_++) {
                size_t row = mrow0 + wm * 64 + mi * 16 + (lane >> 2) + half_ * 8;
                float v0 = acc[mi][n8][half_ * 2 + 0];
                float v1 = acc[mi][n8][half_ * 2 + 1];
                size_t off = row * N + col;
                if (EPI == 0) {
                    *(float2*)(C + off) = make_float2(v0, v1);
                } else if (EPI == 1) {
                    float2 bia = *(const float2*)(bias + col);
                    float2 lb  = *(const float2*)(aux3 + col);
                    float2 vel = *(const float2*)(aux1 + off);
                    float2 xv  = *(const float2*)(aux2 + off);
                    float vn0 = fmaf(1.f / (1.f + __expf(-lb.x)), vel.x, v0 + bia.x);
                    float vn1 = fmaf(1.f / (1.f + __expf(-lb.y)), vel.y, v1 + bia.y);
                    *(float2*)(C + off) = make_float2(vn0, vn1);
                    *(float2*)(out2 + off) = make_float2(xv.x + vn0, xv.y + vn1);
                } else if (EPI == 2) {
                    float2 bia = *(const float2*)(bias + col);
                    float t0 = v0 + bia.x, t1 = v1 + bia.y;
                    t0 = 0.5f * t0 * (1.f + tanhf(c0g * (t0 + c1g * t0 * t0 * t0)));
                    t1 = 0.5f * t1 * (1.f + tanhf(c0g * (t1 + c1g * t1 * t1 * t1)));
                    *(__half2*)(o_hi + off) =
                        __halves2half2(__float2half_rn(t0), __float2half_rn(t1));
                } else if (EPI == 3) {
                    float2 bia = *(const float2*)(bias + col);
                    float2 xn  = *(const float2*)(aux1 + off);
                    *(float2*)(C + off) = make_float2(v0 + bia.x + xn.x, v1 + bia.y + xn.y);
                } else {  // EPI == 4: gating. N==2048; 128-wide tile stays in one half.
                    if (col < 1024) {
                        float s0 = 1.f / (1.f + __expf(-v0));
                        float s1 = 1.f / (1.f + __expf(-v1));
                        *(__half2*)(o_hi + row * 1024 + col) =
                            __halves2half2(__float2half_rn(s0), __float2half_rn(s1));
                    } else {
                        int d = col - 1024;
                        float sp0 = aux3[d], sp1 = aux3[d + 1];
                        float sa0 = 1.f / (1.f + __expf(-v0));
                        float sa1 = 1.f / (1.f + __expf(-v1));
                        float a0 = expf(-sp0 * sa0);
                        float a1 = expf(-sp1 * sa1);
                        *(float2*)(C + row * 1024 + d) = make_float2(a0, a1);
                    }
                }
            }
        }
    }
}

// ---------------- launch ----------------
extern "C" void kernel_launch(void* const* d_in, const int* in_sizes, int n_in,
                              void* d_out, int out_size) {
    const float* x          = (const float*)d_in[0];
    const float* velocity   = (const float*)d_in[1];
    const float* pre_norm_w = (const float*)d_in[2];
    const float* conv_k     = (const float*)d_in[3];
    const float* conv_b     = (const float*)d_in[4];
    const float* W_gate     = (const float*)d_in[5];
    const float* W_a        = (const float*)d_in[6];
    const float* lam        = (const float*)d_in[7];
    const float* W_out      = (const float*)d_in[8];
    const float* b_out      = (const float*)d_in[9];
    const float* log_beta   = (const float*)d_in[10];
    const float* ffn_norm_w = (const float*)d_in[11];
    const float* W_ff1      = (const float*)d_in[12];
    const float* b_ff1      = (const float*)d_in[13];
    const float* W_ff2      = (const float*)d_in[14];
    const float* b_ff2      = (const float*)d_in[15];

    float* out1    = (float*)d_out;
    float* out_vel = out1 + BSD;

    __half *p_xn_h, *p_gate, *p_cc_h, *p_nm_h, *p_hd_h, *p_wt_h;
    float *p_a, *p_xnew, *p_splam;
    cudaGetSymbolAddress((void**)&p_xn_h, g_xn_h);
    cudaGetSymbolAddress((void**)&p_gate, g_gate);
    cudaGetSymbolAddress((void**)&p_a, g_a);
    cudaGetSymbolAddress((void**)&p_cc_h, g_cc_h);
    cudaGetSymbolAddress((void**)&p_nm_h, g_nm_h);
    cudaGetSymbolAddress((void**)&p_hd_h, g_hd_h);
    cudaGetSymbolAddress((void**)&p_wt_h, g_wt_h);
    cudaGetSymbolAddress((void**)&p_xnew, g_xnew);
    cudaGetSymbolAddress((void**)&p_splam, g_splam);

    cudaFuncSetAttribute(hgemm<1>, cudaFuncAttributeMaxDynamicSharedMemorySize, GEMM_SMEM);
    cudaFuncSetAttribute(hgemm<2>, cudaFuncAttributeMaxDynamicSharedMemorySize, GEMM_SMEM);
    cudaFuncSetAttribute(hgemm<3>, cudaFuncAttributeMaxDynamicSharedMemorySize, GEMM_SMEM);
    cudaFuncSetAttribute(hgemm<4>, cudaFuncAttributeMaxDynamicSharedMemorySize, GEMM_SMEM);
    constexpr int SCAN_SMEM = SLEN * 256 * sizeof(float2);   // 128 KB
    cudaFuncSetAttribute(gscan_one, cudaFuncAttributeMaxDynamicSharedMemorySize, SCAN_SMEM);

    // weight layout in g_wt_h (elements):
    //   [0,1M) gate  [1M,2M) a  [2M,4M) W_out^T  [4M,8M) W_ff1^T  [8M,12M) W_ff2^T
    const size_t OFF_GA = 0, OFF_OUT = (size_t)2 << 20,
                 OFF_FF1 = (size_t)4 << 20, OFF_FF2 = (size_t)8 << 20;
    transpose_all<<<12288, 256>>>(W_gate, W_a, W_out, W_ff1, W_ff2, p_wt_h);

    // pre-norm -> fp16; splam; clear lookback records
    rmsnorm_h<<<MM, 256>>>(x, pre_norm_w, p_xn_h);
    splam_kernel<<<4, 256>>>(lam);
    clear_rec<<<BB * SCH * DD / 256, 256>>>();

    // fused gate+a GEMM (M=8192, N=2048, K=1024) with gating epilogue
    dim3 gGA(2048 / 128, MM / 128);
    hgemm<4><<<gGA, 256, GEMM_SMEM>>>(p_xn_h, p_wt_h + OFF_GA,
                                      p_a, 2048, 1024,
                                      nullptr, nullptr, nullptr, p_splam, nullptr, p_gate);

    // single-pass conv + gating + scan (decoupled lookback)
    gscan_one<<<BB * SCH * (DD / 256), 256, SCAN_SMEM>>>(conv_k, conv_b);

    // mixer GEMM (K=2048) + velocity + residual
    dim3 gD(1024 / 128, MM / 128);
    hgemm<1><<<gD, 256, GEMM_SMEM>>>(p_cc_h, p_wt_h + OFF_OUT,
                                     out_vel, 1024, 2048,
                                     b_out, velocity, x, log_beta, p_xnew, nullptr);

    // ffn norm
    rmsnorm_h<<<MM, 256>>>(p_xnew, ffn_norm_w, p_nm_h);

    // ff1 + gelu -> fp16 hidden (N=4096, K=1024)
    dim3 gF(4096 / 128, MM / 128);
    hgemm<2><<<gF, 256, GEMM_SMEM>>>(p_nm_h, p_wt_h + OFF_FF1,
                                     nullptr, 4096, 1024,
                                     b_ff1, nullptr, nullptr, nullptr, nullptr, p_hd_h);

    // ff2 + residual (K=4096) -> out1
    hgemm<3><<<gD, 256, GEMM_SMEM>>>(p_hd_h, p_wt_h + OFF_FF2,
                                     out1, 1024, 4096,
                                     b_ff2, p_xnew, nullptr, nullptr, nullptr, nullptr);
}

// round 11
// speedup vs baseline: 1.4013x; 1.2611x over previous
#include <cuda_runtime.h>
#include <cuda_fp16.h>
#include <math.h>
#include <stdint.h>

// ---------------- problem constants ----------------
constexpr int BB = 4, SSEQ = 2048, DD = 1024, FF = 4096;
constexpr int MM = BB * SSEQ;                 // 8192
constexpr long long BSD = (long long)MM * DD; // 8388608

// ---------------- scratch (device globals; no allocation) ----------------
__device__ __half g_xn_h[MM * DD];
__device__ __half g_gate[MM * DD];            // sigmoid(gate_pre), fp16
__device__ float  g_a[MM * DD];               // recurrence coefficient, fp32
__device__ __half g_cc_h[MM * 2 * DD];        // [conv | griffin_h] fp16
__device__ float  g_xnew[MM * DD];
__device__ __half g_nm_h[MM * DD];
__device__ __half g_hd_h[MM * FF];
__device__ __half g_wt_h[12 * 1024 * 1024];
__device__ float  g_splam[DD];
// decoupled-lookback scan records: 64 chunks x (B*D) channels
constexpr int SCH = 64, SLEN = SSEQ / SCH;    // 64 chunks of 32
__device__ float2 g_recPH[BB * SCH * DD];     // (p, h) partial
__device__ float  g_recI [BB * SCH * DD];     // inclusive H

// ---------------- helpers ----------------
__device__ __forceinline__ uint32_t s2u(const void* p) {
    uint32_t a;
    asm("{ .reg .u64 t; cvta.to.shared.u64 t, %1; cvt.u32.u64 %0, t; }" : "=r"(a) : "l"(p));
    return a;
}
__device__ __forceinline__ void cpasync16(uint32_t saddr, const void* g) {
    asm volatile("cp.async.cg.shared.global [%0], [%1], 16;" :: "r"(saddr), "l"(g));
}
__device__ __forceinline__ void cp_commit() {
    asm volatile("cp.async.commit_group;" ::: "memory");
}
template <int N>
__device__ __forceinline__ void cp_wait() {
    asm volatile("cp.async.wait_group %0;" :: "n"(N) : "memory");
}
__device__ __forceinline__ void ldsm4(uint32_t* r, uint32_t addr) {
    asm volatile("ldmatrix.sync.aligned.m8n8.x4.shared.b16 {%0,%1,%2,%3}, [%4];"
                 : "=r"(r[0]), "=r"(r[1]), "=r"(r[2]), "=r"(r[3]) : "r"(addr));
}
__device__ __forceinline__ void mma16816(float* d, const uint32_t* a, const uint32_t* b) {
    asm volatile(
        "mma.sync.aligned.m16n8k16.row.col.f32.f16.f16.f32 "
        "{%0,%1,%2,%3}, {%4,%5,%6,%7}, {%8,%9}, {%0,%1,%2,%3};"
        : "+f"(d[0]), "+f"(d[1]), "+f"(d[2]), "+f"(d[3])
        : "r"(a[0]), "r"(a[1]), "r"(a[2]), "r"(a[3]), "r"(b[0]), "r"(b[1]));
}
// L2-level (device-visible) 8B/4B load/store for lookback protocol
__device__ __forceinline__ float2 ldcg2(const float2* p) {
    float2 v;
    asm volatile("ld.global.cg.v2.f32 {%0,%1}, [%2];" : "=f"(v.x), "=f"(v.y) : "l"(p));
    return v;
}
__device__ __forceinline__ void stcg2(float2* p, float2 v) {
    asm volatile("st.global.cg.v2.f32 [%0], {%1,%2};" :: "l"(p), "f"(v.x), "f"(v.y) : "memory");
}
__device__ __forceinline__ float ldcg1(const float* p) {
    float v;
    asm volatile("ld.global.cg.f32 %0, [%1];" : "=f"(v) : "l"(p));
    return v;
}
__device__ __forceinline__ void stcg1(float* p, float v) {
    asm volatile("st.global.cg.f32 [%0], %1;" :: "l"(p), "f"(v) : "memory");
}

// ------- merged weight transpose: all 5 weights, one launch -------
__global__ void transpose_all(const float* __restrict__ Wg, const float* __restrict__ Wa,
                              const float* __restrict__ Wo, const float* __restrict__ W1,
                              const float* __restrict__ W2, __half* __restrict__ out) {
    int b = blockIdx.x;
    const float* W;
    int K, N;
    size_t off;
    int tile;
    if (b < 1024)      { W = Wg; K = 1024; N = 1024; off = 0;               tile = b; }
    else if (b < 2048) { W = Wa; K = 1024; N = 1024; off = (size_t)1 << 20; tile = b - 1024; }
    else if (b < 4096) { W = Wo; K = 2048; N = 1024; off = (size_t)2 << 20; tile = b - 2048; }
    else if (b < 8192) { W = W1; K = 1024; N = 4096; off = (size_t)4 << 20; tile = b - 4096; }
    else               { W = W2; K = 4096; N = 1024; off = (size_t)8 << 20; tile = b - 8192; }
    int ntn = N >> 5;
    int n0 = (tile % ntn) * 32, k0 = (tile / ntn) * 32;
    __half* oh = out + off;

    __shared__ float t[32][33];
    int tid = threadIdx.x;
    #pragma unroll
    for (int i = 0; i < 4; i++) {
        int idx = tid + i * 256;
        int kr = idx >> 5, nc = idx & 31;
        t[kr][nc] = W[(size_t)(k0 + kr) * N + n0 + nc];
    }
    __syncthreads();
    #pragma unroll
    for (int i = 0; i < 2; i++) {
        int idx = tid + i * 256;
        int nr = idx >> 4, kp = idx & 15;
        float v0 = t[kp * 2][nr], v1 = t[kp * 2 + 1][nr];
        size_t o = (size_t)(n0 + nr) * K + k0 + kp * 2;
        *(__half2*)(oh + o) = __halves2half2(__float2half_rn(v0), __float2half_rn(v1));
    }
}

// ---------------- rmsnorm -> fp16 ----------------
__global__ void rmsnorm_h(const float* __restrict__ in, const float* __restrict__ w,
                          __half* __restrict__ oh) {
    int row = blockIdx.x;
    const float4* ip = (const float4*)(in + (size_t)row * DD);
    float4 v = ip[threadIdx.x];
    float ss = v.x * v.x + v.y * v.y + v.z * v.z + v.w * v.w;
    #pragma unroll
    for (int o = 16; o > 0; o >>= 1) ss += __shfl_xor_sync(0xffffffffu, ss, o);
    __shared__ float ws[8];
    int lane = threadIdx.x & 31, wid = threadIdx.x >> 5;
    if (lane == 0) ws[wid] = ss;
    __syncthreads();
    if (wid == 0) {
        float s = (lane < 8) ? ws[lane] : 0.f;
        #pragma unroll
        for (int o = 4; o > 0; o >>= 1) s += __shfl_xor_sync(0xffffffffu, s, o);
        if (lane == 0) ws[0] = s;
    }
    __syncthreads();
    float rms = rsqrtf(ws[0] * (1.0f / DD) + 1e-6f);
    float4 wv = ((const float4*)w)[threadIdx.x];
    size_t o0 = (size_t)row * DD + threadIdx.x * 4;
    *(__half2*)(oh + o0)     = __halves2half2(__float2half_rn(v.x * rms * wv.x),
                                              __float2half_rn(v.y * rms * wv.y));
    *(__half2*)(oh + o0 + 2) = __halves2half2(__float2half_rn(v.z * rms * wv.z),
                                              __float2half_rn(v.w * rms * wv.w));
}

// ---------------- splam[d] = 8 * softplus(lam[d]) ----------------
__global__ void splam_kernel(const float* __restrict__ lam) {
    int d = blockIdx.x * blockDim.x + threadIdx.x;
    if (d < DD) {
        float l = lam[d];
        float sp = (l > 20.f) ? l : log1pf(expf(l));
        g_splam[d] = 8.0f * sp;
    }
}

// ------- clear lookback records to NaN sentinel (fresh each launch) -------
__global__ void clear_rec() {
    int i = blockIdx.x * 256 + threadIdx.x;   // < BB*SCH*DD = 262144
    float nf = __int_as_float(0x7fffffff);
    g_recPH[i] = make_float2(nf, nf);
    g_recI[i] = nf;
}

// ------- single-pass scan: conv + u + chunk scan + decoupled lookback -------
// block = (ch, b, dblk); thread owns one d; chunk (a,u) staged in smem (64 KB).
// Predecessor chunks have LOWER blockIdx (forward-progress per CUB model).
__global__ void __launch_bounds__(256) gscan_one(const float* __restrict__ ck,
                                                 const float* __restrict__ cb) {
    extern __shared__ float2 au[];            // [SLEN][256]
    int tid = threadIdx.x;
    int bid = blockIdx.x;                     // ch*16 + b*4 + dblk
    int ch = bid >> 4;
    int b = (bid >> 2) & 3;
    int dblk = bid & 3;
    int d = dblk * 256 + tid;

    float4 kv = ((const float4*)ck)[d];
    float cbias = cb[d];

    long long r0 = (long long)b * SSEQ + ch * SLEN;
    long long xbase = r0 * DD + d;
    float xm1 = 0.f, xm2 = 0.f, xm3 = 0.f;
    if (ch > 0) {
        xm1 = __half2float(g_xn_h[xbase - DD]);
        xm2 = __half2float(g_xn_h[xbase - 2 * DD]);
        xm3 = __half2float(g_xn_h[xbase - 3 * DD]);
    }
    float p = 1.f, h = 0.f;
    #pragma unroll 4
    for (int t = 0; t < SLEN; t++) {
        long long i = xbase + (long long)t * DD;
        float xn = __half2float(g_xn_h[i]);
        float conv = cbias + kv.x * xn + kv.y * xm1 + kv.z * xm2 + kv.w * xm3;
        float gate = __half2float(g_gate[i]);
        float a = g_a[i];
        float u = sqrtf(fmaxf(1.f - a * a, 0.f)) * gate * xn;
        g_cc_h[(r0 + t) * (2 * DD) + d] = __float2half_rn(conv);
        au[t * 256 + tid] = make_float2(a, u);
        p *= a;
        h = fmaf(a, h, u);
        xm3 = xm2; xm2 = xm1; xm1 = xn;
    }

    int recbase = b * SCH * DD + d;           // + ch*DD per chunk
    stcg2(&g_recPH[recbase + ch * DD], make_float2(p, h));   // publish partial (8B atomic)

    // decoupled lookback: resolve carry C = inclusive H of chunk ch-1
    float C = 0.f;
    if (ch > 0) {
        float accP = 1.f, accH = 0.f;
        int look = ch - 1;
        while (true) {
            float hi = ldcg1(&g_recI[recbase + look * DD]);
            if (!isnan(hi)) { C = fmaf(accP, hi, accH); break; }
            float2 ph = ldcg2(&g_recPH[recbase + look * DD]);
            if (!isnan(ph.x)) {
                accH = fmaf(accP, ph.y, accH);
                accP *= ph.x;
                if (--look < 0) { C = accH; break; }
            }
        }
    }
    stcg1(&g_recI[recbase + ch * DD], fmaf(p, C, h));        // publish inclusive

    // phase 2: replay chunk from smem with carry
    h = C;
    #pragma unroll 4
    for (int t = 0; t < SLEN; t++) {
        float2 v = au[t * 256 + tid];
        h = fmaf(v.x, h, v.y);
        g_cc_h[(r0 + t) * (2 * DD) + DD + d] = __float2half_rn(h);
    }
}

// ------- HMMA GEMM: 128x128 tile, 8 warps, 64x32 warp tiles, BK=64 -------
// 3-stage cp.async (32 KB/stage), 2 CTAs/SM. grid: x = N-blocks, y = M-blocks.
// 128B-row swizzle: chunk ^= (row & 7).
// EPI: 0 plain fp32; 1 mixer; 2 gelu->fp16; 3 +bias+aux residual;
//      4 gating (gate->fp16 o_hi, a=exp(-splam*sigmoid)->fp32 C, N-stride 1024)
constexpr int STG = 32768;           // A 16K | B 16K
constexpr int GEMM_SMEM = 3 * STG;   // 96 KB

template <int EPI>
__global__ void __launch_bounds__(256)
hgemm(const __half* __restrict__ Ah, const __half* __restrict__ Bh,
      float* __restrict__ C, int N, int K,
      const float* __restrict__ bias,
      const float* __restrict__ aux1, const float* __restrict__ aux2,
      const float* __restrict__ aux3,
      float* __restrict__ out2,
      __half* __restrict__ o_hi) {
    extern __shared__ char sm[];
    uint32_t sb = s2u(sm);
    int tid = threadIdx.x;
    int lane = tid & 31, wid = tid >> 5;
    int wm = wid >> 2, wn = wid & 3;          // warp tile 64x32 at (wm*64, wn*32)
    size_t mrow0 = (size_t)blockIdx.y * 128;
    size_t ncol0 = (size_t)blockIdx.x * 128;

    float acc[4][4][4];
    #pragma unroll
    for (int a = 0; a < 4; a++)
        #pragma unroll
        for (int b = 0; b < 4; b++)
            #pragma unroll
            for (int c = 0; c < 4; c++) acc[a][b][c] = 0.f;

    auto load_stage = [&](int s, int k0) {
        uint32_t base = sb + s * STG;
        // A and B: each 128 rows x 128B = 1024 16B-chunks; 256 threads x 4
        #pragma unroll
        for (int i = 0; i < 4; i++) {
            int idx = tid + i * 256;
            int r = idx >> 3, c = idx & 7;
            uint32_t sw = r * 128 + ((c ^ (r & 7)) << 4);
            cpasync16(base + sw, Ah + (mrow0 + r) * K + k0 + c * 8);
            cpasync16(base + 16384 + sw, Bh + (ncol0 + r) * K + k0 + c * 8);
        }
    };

    const int KT = K >> 6;  // BK = 64
    load_stage(0, 0);
    cp_commit();
    load_stage(1, 64);
    cp_commit();

    for (int kt = 0; kt < KT; kt++) {
        if (kt + 1 < KT) cp_wait<1>(); else cp_wait<0>();
        __syncthreads();
        if (kt + 2 < KT) {
            int s = kt + 2;
            load_stage(s % 3, s << 6);
            cp_commit();
        }
        uint32_t base = sb + (kt % 3) * STG;
        #pragma unroll
        for (int kk = 0; kk < 4; kk++) {
            uint32_t ah[4][4], bh[2][4];
            int g = lane >> 3;
            int ar = (lane & 7) + ((g & 1) << 3);
            int ac = kk * 2 + (g >> 1);
            #pragma unroll
            for (int mi = 0; mi < 4; mi++) {
                int row = wm * 64 + mi * 16 + ar;
                uint32_t off = row * 128 + ((ac ^ (row & 7)) << 4);
                ldsm4(ah[mi], base + off);
            }
            int br = (lane & 7) + ((g >> 1) << 3);
            int bc = kk * 2 + (g & 1);
            #pragma unroll
            for (int ni = 0; ni < 2; ni++) {
                int row = wn * 32 + ni * 16 + br;
                uint32_t off = row * 128 + ((bc ^ (row & 7)) << 4);
                ldsm4(bh[ni], base + 16384 + off);
            }
            #pragma unroll
            for (int mi = 0; mi < 4; mi++)
                #pragma unroll
                for (int n8 = 0; n8 < 4; n8++)
                    mma16816(acc[mi][n8], ah[mi], &bh[n8 >> 1][(n8 & 1) * 2]);
        }
    }

    // ---------------- epilogue ----------------
    const float c0g = 0.7978845608028654f, c1g = 0.044715f;
    #pragma unroll
    for (int mi = 0; mi < 4; mi++) {
        #pragma unroll
        for (int n8 = 0; n8 < 4; n8++) {
            int col = (int)ncol0 + wn * 32 + n8 * 8 + (lane & 3) * 2;
            #pragma unroll
            for (int half_ = 0; half_ < 2; half_++) {
                size_t row = mrow0 + wm * 64 + mi * 16 + (lane >> 2) + half_ * 8;
                float v0 = acc[mi][n8][half_ * 2 + 0];
                float v1 = acc[mi][n8][half_ * 2 + 1];
                size_t off = row * N + col;
                if (EPI == 0) {
                    *(float2*)(C + off) = make_float2(v0, v1);
                } else if (EPI == 1) {
                    float2 bia = *(const float2*)(bias + col);
                    float2 lb  = *(const float2*)(aux3 + col);
                    float2 vel = *(const float2*)(aux1 + off);
                    float2 xv  = *(const float2*)(aux2 + off);
                    float vn0 = fmaf(1.f / (1.f + __expf(-lb.x)), vel.x, v0 + bia.x);
                    float vn1 = fmaf(1.f / (1.f + __expf(-lb.y)), vel.y, v1 + bia.y);
                    *(float2*)(C + off) = make_float2(vn0, vn1);
                    *(float2*)(out2 + off) = make_float2(xv.x + vn0, xv.y + vn1);
                } else if (EPI == 2) {
                    float2 bia = *(const float2*)(bias + col);
                    float t0 = v0 + bia.x, t1 = v1 + bia.y;
                    t0 = 0.5f * t0 * (1.f + tanhf(c0g * (t0 + c1g * t0 * t0 * t0)));
                    t1 = 0.5f * t1 * (1.f + tanhf(c0g * (t1 + c1g * t1 * t1 * t1)));
                    *(__half2*)(o_hi + off) =
                        __halves2half2(__float2half_rn(t0), __float2half_rn(t1));
                } else if (EPI == 3) {
                    float2 bia = *(const float2*)(bias + col);
                    float2 xn  = *(const float2*)(aux1 + off);
                    *(float2*)(C + off) = make_float2(v0 + bia.x + xn.x, v1 + bia.y + xn.y);
                } else {  // EPI == 4: gating. N==2048; 128-wide tile stays in one half.
                    if (col < 1024) {
                        float s0 = 1.f / (1.f + __expf(-v0));
                        float s1 = 1.f / (1.f + __expf(-v1));
                        *(__half2*)(o_hi + row * 1024 + col) =
                            __halves2half2(__float2half_rn(s0), __float2half_rn(s1));
                    } else {
                        int d = col - 1024;
                        float sp0 = aux3[d], sp1 = aux3[d + 1];
                        float sa0 = 1.f / (1.f + __expf(-v0));
                        float sa1 = 1.f / (1.f + __expf(-v1));
                        float a0 = expf(-sp0 * sa0);
                        float a1 = expf(-sp1 * sa1);
                        *(float2*)(C + row * 1024 + d) = make_float2(a0, a1);
                    }
                }
            }
        }
    }
}

// ---------------- launch ----------------
extern "C" void kernel_launch(void* const* d_in, const int* in_sizes, int n_in,
                              void* d_out, int out_size) {
    const float* x          = (const float*)d_in[0];
    const float* velocity   = (const float*)d_in[1];
    const float* pre_norm_w = (const float*)d_in[2];
    const float* conv_k     = (const float*)d_in[3];
    const float* conv_b     = (const float*)d_in[4];
    const float* W_gate     = (const float*)d_in[5];
    const float* W_a        = (const float*)d_in[6];
    const float* lam        = (const float*)d_in[7];
    const float* W_out      = (const float*)d_in[8];
    const float* b_out      = (const float*)d_in[9];
    const float* log_beta   = (const float*)d_in[10];
    const float* ffn_norm_w = (const float*)d_in[11];
    const float* W_ff1      = (const float*)d_in[12];
    const float* b_ff1      = (const float*)d_in[13];
    const float* W_ff2      = (const float*)d_in[14];
    const float* b_ff2      = (const float*)d_in[15];

    float* out1    = (float*)d_out;
    float* out_vel = out1 + BSD;

    __half *p_xn_h, *p_gate, *p_cc_h, *p_nm_h, *p_hd_h, *p_wt_h;
    float *p_a, *p_xnew, *p_splam;
    cudaGetSymbolAddress((void**)&p_xn_h, g_xn_h);
    cudaGetSymbolAddress((void**)&p_gate, g_gate);
    cudaGetSymbolAddress((void**)&p_a, g_a);
    cudaGetSymbolAddress((void**)&p_cc_h, g_cc_h);
    cudaGetSymbolAddress((void**)&p_nm_h, g_nm_h);
    cudaGetSymbolAddress((void**)&p_hd_h, g_hd_h);
    cudaGetSymbolAddress((void**)&p_wt_h, g_wt_h);
    cudaGetSymbolAddress((void**)&p_xnew, g_xnew);
    cudaGetSymbolAddress((void**)&p_splam, g_splam);

    cudaFuncSetAttribute(hgemm<1>, cudaFuncAttributeMaxDynamicSharedMemorySize, GEMM_SMEM);
    cudaFuncSetAttribute(hgemm<2>, cudaFuncAttributeMaxDynamicSharedMemorySize, GEMM_SMEM);
    cudaFuncSetAttribute(hgemm<3>, cudaFuncAttributeMaxDynamicSharedMemorySize, GEMM_SMEM);
    cudaFuncSetAttribute(hgemm<4>, cudaFuncAttributeMaxDynamicSharedMemorySize, GEMM_SMEM);
    constexpr int SCAN_SMEM = SLEN * 256 * sizeof(float2);   // 64 KB
    cudaFuncSetAttribute(gscan_one, cudaFuncAttributeMaxDynamicSharedMemorySize, SCAN_SMEM);

    // weight layout in g_wt_h (elements):
    //   [0,1M) gate  [1M,2M) a  [2M,4M) W_out^T  [4M,8M) W_ff1^T  [8M,12M) W_ff2^T
    const size_t OFF_GA = 0, OFF_OUT = (size_t)2 << 20,
                 OFF_FF1 = (size_t)4 << 20, OFF_FF2 = (size_t)8 << 20;
    transpose_all<<<12288, 256>>>(W_gate, W_a, W_out, W_ff1, W_ff2, p_wt_h);

    // pre-norm -> fp16; splam; clear lookback records
    rmsnorm_h<<<MM, 256>>>(x, pre_norm_w, p_xn_h);
    splam_kernel<<<4, 256>>>(lam);
    clear_rec<<<BB * SCH * DD / 256, 256>>>();

    // fused gate+a GEMM (M=8192, N=2048, K=1024) with gating epilogue
    dim3 gGA(2048 / 128, MM / 128);
    hgemm<4><<<gGA, 256, GEMM_SMEM>>>(p_xn_h, p_wt_h + OFF_GA,
                                      p_a, 2048, 1024,
                                      nullptr, nullptr, nullptr, p_splam, nullptr, p_gate);

    // single-pass conv + gating + scan (decoupled lookback)
    gscan_one<<<BB * SCH * (DD / 256), 256, SCAN_SMEM>>>(conv_k, conv_b);

    // mixer GEMM (K=2048) + velocity + residual
    dim3 gD(1024 / 128, MM / 128);
    hgemm<1><<<gD, 256, GEMM_SMEM>>>(p_cc_h, p_wt_h + OFF_OUT,
                                     out_vel, 1024, 2048,
                                     b_out, velocity, x, log_beta, p_xnew, nullptr);

    // ffn norm
    rmsnorm_h<<<MM, 256>>>(p_xnew, ffn_norm_w, p_nm_h);

    // ff1 + gelu -> fp16 hidden (N=4096, K=1024)
    dim3 gF(4096 / 128, MM / 128);
    hgemm<2><<<gF, 256, GEMM_SMEM>>>(p_nm_h, p_wt_h + OFF_FF1,
                                     nullptr, 4096, 1024,
                                     b_ff1, nullptr, nullptr, nullptr, nullptr, p_hd_h);

    // ff2 + residual (K=4096) -> out1
    hgemm<3><<<gD, 256, GEMM_SMEM>>>(p_hd_h, p_wt_h + OFF_FF2,
                                     out1, 1024, 4096,
                                     b_ff2, p_xnew, nullptr, nullptr, nullptr, nullptr);
}

// round 12
// speedup vs baseline: 1.4107x; 1.0067x over previous
#include <cuda_runtime.h>
#include <cuda_fp16.h>
#include <math.h>
#include <stdint.h>

// ---------------- problem constants ----------------
constexpr int BB = 4, SSEQ = 2048, DD = 1024, FF = 4096;
constexpr int MM = BB * SSEQ;                 // 8192
constexpr long long BSD = (long long)MM * DD; // 8388608

// ---------------- scratch (device globals; no allocation) ----------------
__device__ __half g_xn_h[MM * DD];
__device__ __half g_gate[MM * DD];            // sigmoid(gate_pre), fp16
__device__ float  g_a[MM * DD];               // recurrence coefficient, fp32
__device__ __half g_cc_h[MM * 2 * DD];        // [conv | griffin_h] fp16
__device__ __half g_xnew_h[MM * DD];          // x + velocity_new, fp16
__device__ __half g_nm_h[MM * DD];
__device__ __half g_hd_h[MM * FF];
__device__ __half g_wt_h[12 * 1024 * 1024];
__device__ float  g_splam[DD];
// decoupled-lookback scan records: 64 chunks x (B*D) channels
constexpr int SCH = 64, SLEN = SSEQ / SCH;    // 64 chunks of 32
__device__ float2 g_recPH[BB * SCH * DD];     // (p, h) partial
__device__ float  g_recI [BB * SCH * DD];     // inclusive H

// ---------------- helpers ----------------
__device__ __forceinline__ uint32_t s2u(const void* p) {
    uint32_t a;
    asm("{ .reg .u64 t; cvta.to.shared.u64 t, %1; cvt.u32.u64 %0, t; }" : "=r"(a) : "l"(p));
    return a;
}
__device__ __forceinline__ void cpasync16(uint32_t saddr, const void* g) {
    asm volatile("cp.async.cg.shared.global [%0], [%1], 16;" :: "r"(saddr), "l"(g));
}
__device__ __forceinline__ void cp_commit() {
    asm volatile("cp.async.commit_group;" ::: "memory");
}
template <int N>
__device__ __forceinline__ void cp_wait() {
    asm volatile("cp.async.wait_group %0;" :: "n"(N) : "memory");
}
__device__ __forceinline__ void ldsm4(uint32_t* r, uint32_t addr) {
    asm volatile("ldmatrix.sync.aligned.m8n8.x4.shared.b16 {%0,%1,%2,%3}, [%4];"
                 : "=r"(r[0]), "=r"(r[1]), "=r"(r[2]), "=r"(r[3]) : "r"(addr));
}
__device__ __forceinline__ void mma16816(float* d, const uint32_t* a, const uint32_t* b) {
    asm volatile(
        "mma.sync.aligned.m16n8k16.row.col.f32.f16.f16.f32 "
        "{%0,%1,%2,%3}, {%4,%5,%6,%7}, {%8,%9}, {%0,%1,%2,%3};"
        : "+f"(d[0]), "+f"(d[1]), "+f"(d[2]), "+f"(d[3])
        : "r"(a[0]), "r"(a[1]), "r"(a[2]), "r"(a[3]), "r"(b[0]), "r"(b[1]));
}
__device__ __forceinline__ float2 ldcg2(const float2* p) {
    float2 v;
    asm volatile("ld.global.cg.v2.f32 {%0,%1}, [%2];" : "=f"(v.x), "=f"(v.y) : "l"(p));
    return v;
}
__device__ __forceinline__ void stcg2(float2* p, float2 v) {
    asm volatile("st.global.cg.v2.f32 [%0], {%1,%2};" :: "l"(p), "f"(v.x), "f"(v.y) : "memory");
}
__device__ __forceinline__ float ldcg1(const float* p) {
    float v;
    asm volatile("ld.global.cg.f32 %0, [%1];" : "=f"(v) : "l"(p));
    return v;
}
__device__ __forceinline__ void stcg1(float* p, float v) {
    asm volatile("st.global.cg.f32 [%0], %1;" :: "l"(p), "f"(v) : "memory");
}

// ------- weight transpose (block-offset param so it can be split) -------
__global__ void transpose_all(const float* __restrict__ Wg, const float* __restrict__ Wa,
                              const float* __restrict__ Wo, const float* __restrict__ W1,
                              const float* __restrict__ W2, __half* __restrict__ out,
                              int boff) {
    int b = blockIdx.x + boff;
    const float* W;
    int K, N;
    size_t off;
    int tile;
    if (b < 1024)      { W = Wg; K = 1024; N = 1024; off = 0;               tile = b; }
    else if (b < 2048) { W = Wa; K = 1024; N = 1024; off = (size_t)1 << 20; tile = b - 1024; }
    else if (b < 4096) { W = Wo; K = 2048; N = 1024; off = (size_t)2 << 20; tile = b - 2048; }
    else if (b < 8192) { W = W1; K = 1024; N = 4096; off = (size_t)4 << 20; tile = b - 4096; }
    else               { W = W2; K = 4096; N = 1024; off = (size_t)8 << 20; tile = b - 8192; }
    int ntn = N >> 5;
    int n0 = (tile % ntn) * 32, k0 = (tile / ntn) * 32;
    __half* oh = out + off;

    __shared__ float t[32][33];
    int tid = threadIdx.x;
    #pragma unroll
    for (int i = 0; i < 4; i++) {
        int idx = tid + i * 256;
        int kr = idx >> 5, nc = idx & 31;
        t[kr][nc] = W[(size_t)(k0 + kr) * N + n0 + nc];
    }
    __syncthreads();
    #pragma unroll
    for (int i = 0; i < 2; i++) {
        int idx = tid + i * 256;
        int nr = idx >> 4, kp = idx & 15;
        float v0 = t[kp * 2][nr], v1 = t[kp * 2 + 1][nr];
        size_t o = (size_t)(n0 + nr) * K + k0 + kp * 2;
        *(__half2*)(oh + o) = __halves2half2(__float2half_rn(v0), __float2half_rn(v1));
    }
}

// ---------------- rmsnorm (fp32 in) -> fp16 ----------------
__global__ void rmsnorm_h(const float* __restrict__ in, const float* __restrict__ w,
                          __half* __restrict__ oh) {
    int row = blockIdx.x;
    const float4* ip = (const float4*)(in + (size_t)row * DD);
    float4 v = ip[threadIdx.x];
    float ss = v.x * v.x + v.y * v.y + v.z * v.z + v.w * v.w;
    #pragma unroll
    for (int o = 16; o > 0; o >>= 1) ss += __shfl_xor_sync(0xffffffffu, ss, o);
    __shared__ float ws[8];
    int lane = threadIdx.x & 31, wid = threadIdx.x >> 5;
    if (lane == 0) ws[wid] = ss;
    __syncthreads();
    if (wid == 0) {
        float s = (lane < 8) ? ws[lane] : 0.f;
        #pragma unroll
        for (int o = 4; o > 0; o >>= 1) s += __shfl_xor_sync(0xffffffffu, s, o);
        if (lane == 0) ws[0] = s;
    }
    __syncthreads();
    float rms = rsqrtf(ws[0] * (1.0f / DD) + 1e-6f);
    float4 wv = ((const float4*)w)[threadIdx.x];
    size_t o0 = (size_t)row * DD + threadIdx.x * 4;
    *(__half2*)(oh + o0)     = __halves2half2(__float2half_rn(v.x * rms * wv.x),
                                              __float2half_rn(v.y * rms * wv.y));
    *(__half2*)(oh + o0 + 2) = __halves2half2(__float2half_rn(v.z * rms * wv.z),
                                              __float2half_rn(v.w * rms * wv.w));
}

// ---------------- rmsnorm (fp16 in) -> fp16 ----------------
__global__ void rmsnorm_h16(const __half* __restrict__ in, const float* __restrict__ w,
                            __half* __restrict__ oh) {
    int row = blockIdx.x;
    const __half2* ip = (const __half2*)(in + (size_t)row * DD);
    __half2 h0 = ip[threadIdx.x * 2], h1 = ip[threadIdx.x * 2 + 1];
    float x0 = __half2float(h0.x), x1 = __half2float(h0.y);
    float x2 = __half2float(h1.x), x3 = __half2float(h1.y);
    float ss = x0 * x0 + x1 * x1 + x2 * x2 + x3 * x3;
    #pragma unroll
    for (int o = 16; o > 0; o >>= 1) ss += __shfl_xor_sync(0xffffffffu, ss, o);
    __shared__ float ws[8];
    int lane = threadIdx.x & 31, wid = threadIdx.x >> 5;
    if (lane == 0) ws[wid] = ss;
    __syncthreads();
    if (wid == 0) {
        float s = (lane < 8) ? ws[lane] : 0.f;
        #pragma unroll
        for (int o = 4; o > 0; o >>= 1) s += __shfl_xor_sync(0xffffffffu, s, o);
        if (lane == 0) ws[0] = s;
    }
    __syncthreads();
    float rms = rsqrtf(ws[0] * (1.0f / DD) + 1e-6f);
    float4 wv = ((const float4*)w)[threadIdx.x];
    size_t o0 = (size_t)row * DD + threadIdx.x * 4;
    *(__half2*)(oh + o0)     = __halves2half2(__float2half_rn(x0 * rms * wv.x),
                                              __float2half_rn(x1 * rms * wv.y));
    *(__half2*)(oh + o0 + 2) = __halves2half2(__float2half_rn(x2 * rms * wv.z),
                                              __float2half_rn(x3 * rms * wv.w));
}

// ------- prologue: clear lookback records + splam -------
__global__ void prologue(const float* __restrict__ lam) {
    int i = blockIdx.x * 256 + threadIdx.x;   // < BB*SCH*DD = 262144
    float nf = __int_as_float(0x7fffffff);
    g_recPH[i] = make_float2(nf, nf);
    g_recI[i] = nf;
    if (i < DD) {
        float l = lam[i];
        float sp = (l > 20.f) ? l : log1pf(expf(l));
        g_splam[i] = 8.0f * sp;
    }
}

// ------- single-pass scan: conv + u + chunk scan + decoupled lookback -------
__global__ void __launch_bounds__(256) gscan_one(const float* __restrict__ ck,
                                                 const float* __restrict__ cb) {
    extern __shared__ float2 au[];            // [SLEN][256]
    int tid = threadIdx.x;
    int bid = blockIdx.x;                     // ch*16 + b*4 + dblk
    int ch = bid >> 4;
    int b = (bid >> 2) & 3;
    int dblk = bid & 3;
    int d = dblk * 256 + tid;

    float4 kv = ((const float4*)ck)[d];
    float cbias = cb[d];

    long long r0 = (long long)b * SSEQ + ch * SLEN;
    long long xbase = r0 * DD + d;
    float xm1 = 0.f, xm2 = 0.f, xm3 = 0.f;
    if (ch > 0) {
        xm1 = __half2float(g_xn_h[xbase - DD]);
        xm2 = __half2float(g_xn_h[xbase - 2 * DD]);
        xm3 = __half2float(g_xn_h[xbase - 3 * DD]);
    }
    float p = 1.f, h = 0.f;
    #pragma unroll 4
    for (int t = 0; t < SLEN; t++) {
        long long i = xbase + (long long)t * DD;
        float xn = __half2float(g_xn_h[i]);
        float conv = cbias + kv.x * xn + kv.y * xm1 + kv.z * xm2 + kv.w * xm3;
        float gate = __half2float(g_gate[i]);
        float a = g_a[i];
        float u = sqrtf(fmaxf(1.f - a * a, 0.f)) * gate * xn;
        g_cc_h[(r0 + t) * (2 * DD) + d] = __float2half_rn(conv);
        au[t * 256 + tid] = make_float2(a, u);
        p *= a;
        h = fmaf(a, h, u);
        xm3 = xm2; xm2 = xm1; xm1 = xn;
    }

    int recbase = b * SCH * DD + d;
    stcg2(&g_recPH[recbase + ch * DD], make_float2(p, h));

    float C = 0.f;
    if (ch > 0) {
        float accP = 1.f, accH = 0.f;
        int look = ch - 1;
        while (true) {
            float hi = ldcg1(&g_recI[recbase + look * DD]);
            if (!isnan(hi)) { C = fmaf(accP, hi, accH); break; }
            float2 ph = ldcg2(&g_recPH[recbase + look * DD]);
            if (!isnan(ph.x)) {
                accH = fmaf(accP, ph.y, accH);
                accP *= ph.x;
                if (--look < 0) { C = accH; break; }
            }
        }
    }
    stcg1(&g_recI[recbase + ch * DD], fmaf(p, C, h));

    h = C;
    #pragma unroll 4
    for (int t = 0; t < SLEN; t++) {
        float2 v = au[t * 256 + tid];
        h = fmaf(v.x, h, v.y);
        g_cc_h[(r0 + t) * (2 * DD) + DD + d] = __float2half_rn(h);
    }
}

// ------- HMMA GEMM: 128x128 tile, 8 warps, 64x32 warp tiles, BK=64 -------
// 3-stage cp.async (32 KB/stage), 2 CTAs/SM. grid: x = N-blocks, y = M-blocks.
// EPI: 1 mixer (xnew -> fp16 out2h); 2 gelu->fp16; 3 +bias + fp16 aux residual;
//      4 gating (gate->fp16 auxh, a->fp32 C, N-stride 1024)
constexpr int STG = 32768;           // A 16K | B 16K
constexpr int GEMM_SMEM = 3 * STG;   // 96 KB

template <int EPI>
__global__ void __launch_bounds__(256)
hgemm(const __half* __restrict__ Ah, const __half* __restrict__ Bh,
      float* __restrict__ C, int N, int K,
      const float* __restrict__ bias,
      const float* __restrict__ aux1, const float* __restrict__ aux2,
      const float* __restrict__ aux3,
      __half* __restrict__ out2h,
      __half* __restrict__ auxh) {
    extern __shared__ char sm[];
    uint32_t sb = s2u(sm);
    int tid = threadIdx.x;
    int lane = tid & 31, wid = tid >> 5;
    int wm = wid >> 2, wn = wid & 3;          // warp tile 64x32
    size_t mrow0 = (size_t)blockIdx.y * 128;
    size_t ncol0 = (size_t)blockIdx.x * 128;

    float acc[4][4][4];
    #pragma unroll
    for (int a = 0; a < 4; a++)
        #pragma unroll
        for (int b = 0; b < 4; b++)
            #pragma unroll
            for (int c = 0; c < 4; c++) acc[a][b][c] = 0.f;

    auto load_stage = [&](int s, int k0) {
        uint32_t base = sb + s * STG;
        #pragma unroll
        for (int i = 0; i < 4; i++) {
            int idx = tid + i * 256;
            int r = idx >> 3, c = idx & 7;
            uint32_t sw = r * 128 + ((c ^ (r & 7)) << 4);
            cpasync16(base + sw, Ah + (mrow0 + r) * K + k0 + c * 8);
            cpasync16(base + 16384 + sw, Bh + (ncol0 + r) * K + k0 + c * 8);
        }
    };

    const int KT = K >> 6;  // BK = 64
    load_stage(0, 0);
    cp_commit();
    load_stage(1, 64);
    cp_commit();

    for (int kt = 0; kt < KT; kt++) {
        if (kt + 1 < KT) cp_wait<1>(); else cp_wait<0>();
        __syncthreads();
        if (kt + 2 < KT) {
            int s = kt + 2;
            load_stage(s % 3, s << 6);
            cp_commit();
        }
        uint32_t base = sb + (kt % 3) * STG;
        #pragma unroll
        for (int kk = 0; kk < 4; kk++) {
            uint32_t ah[4][4], bh[2][4];
            int g = lane >> 3;
            int ar = (lane & 7) + ((g & 1) << 3);
            int ac = kk * 2 + (g >> 1);
            #pragma unroll
            for (int mi = 0; mi < 4; mi++) {
                int row = wm * 64 + mi * 16 + ar;
                uint32_t off = row * 128 + ((ac ^ (row & 7)) << 4);
                ldsm4(ah[mi], base + off);
            }
            int br = (lane & 7) + ((g >> 1) << 3);
            int bc = kk * 2 + (g & 1);
            #pragma unroll
            for (int ni = 0; ni < 2; ni++) {
                int row = wn * 32 + ni * 16 + br;
                uint32_t off = row * 128 + ((bc ^ (row & 7)) << 4);
                ldsm4(bh[ni], base + 16384 + off);
            }
            #pragma unroll
            for (int mi = 0; mi < 4; mi++)
                #pragma unroll
                for (int n8 = 0; n8 < 4; n8++)
                    mma16816(acc[mi][n8], ah[mi], &bh[n8 >> 1][(n8 & 1) * 2]);
        }
    }

    // ---------------- epilogue ----------------
    const float c0g = 0.7978845608028654f, c1g = 0.044715f;
    #pragma unroll
    for (int mi = 0; mi < 4; mi++) {
        #pragma unroll
        for (int n8 = 0; n8 < 4; n8++) {
            int col = (int)ncol0 + wn * 32 + n8 * 8 + (lane & 3) * 2;
            #pragma unroll
            for (int half_ = 0; half_ < 2; half_++) {
                size_t row = mrow0 + wm * 64 + mi * 16 + (lane >> 2) + half_ * 8;
                float v0 = acc[mi][n8][half_ * 2 + 0];
                float v1 = acc[mi][n8][half_ * 2 + 1];
                size_t off = row * N + col;
                if (EPI == 1) {
                    float2 bia = *(const float2*)(bias + col);
                    float2 lb  = *(const float2*)(aux3 + col);
                    float2 vel = *(const float2*)(aux1 + off);
                    float2 xv  = *(const float2*)(aux2 + off);
                    float vn0 = fmaf(1.f / (1.f + __expf(-lb.x)), vel.x, v0 + bia.x);
                    float vn1 = fmaf(1.f / (1.f + __expf(-lb.y)), vel.y, v1 + bia.y);
                    *(float2*)(C + off) = make_float2(vn0, vn1);
                    *(__half2*)(out2h + off) =
                        __halves2half2(__float2half_rn(xv.x + vn0), __float2half_rn(xv.y + vn1));
                } else if (EPI == 2) {
                    float2 bia = *(const float2*)(bias + col);
                    float t0 = v0 + bia.x, t1 = v1 + bia.y;
                    t0 = 0.5f * t0 * (1.f + tanhf(c0g * (t0 + c1g * t0 * t0 * t0)));
                    t1 = 0.5f * t1 * (1.f + tanhf(c0g * (t1 + c1g * t1 * t1 * t1)));
                    *(__half2*)(out2h + off) =
                        __halves2half2(__float2half_rn(t0), __float2half_rn(t1));
                } else if (EPI == 3) {
                    float2 bia = *(const float2*)(bias + col);
                    __half2 xn2 = *(const __half2*)(auxh + off);
                    *(float2*)(C + off) = make_float2(v0 + bia.x + __half2float(xn2.x),
                                                      v1 + bia.y + __half2float(xn2.y));
                } else {  // EPI == 4: gating. N==2048; tile stays in one half.
                    if (col < 1024) {
                        float s0 = 1.f / (1.f + __expf(-v0));
                        float s1 = 1.f / (1.f + __expf(-v1));
                        *(__half2*)(auxh + row * 1024 + col) =
                            __halves2half2(__float2half_rn(s0), __float2half_rn(s1));
                    } else {
                        int d = col - 1024;
                        float sp0 = aux3[d], sp1 = aux3[d + 1];
                        float sa0 = 1.f / (1.f + __expf(-v0));
                        float sa1 = 1.f / (1.f + __expf(-v1));
                        float a0 = expf(-sp0 * sa0);
                        float a1 = expf(-sp1 * sa1);
                        *(float2*)(C + row * 1024 + d) = make_float2(a0, a1);
                    }
                }
            }
        }
    }
}

// ---------------- launch ----------------
extern "C" void kernel_launch(void* const* d_in, const int* in_sizes, int n_in,
                              void* d_out, int out_size) {
    const float* x          = (const float*)d_in[0];
    const float* velocity   = (const float*)d_in[1];
    const float* pre_norm_w = (const float*)d_in[2];
    const float* conv_k     = (const float*)d_in[3];
    const float* conv_b     = (const float*)d_in[4];
    const float* W_gate     = (const float*)d_in[5];
    const float* W_a        = (const float*)d_in[6];
    const float* lam        = (const float*)d_in[7];
    const float* W_out      = (const float*)d_in[8];
    const float* b_out      = (const float*)d_in[9];
    const float* log_beta   = (const float*)d_in[10];
    const float* ffn_norm_w = (const float*)d_in[11];
    const float* W_ff1      = (const float*)d_in[12];
    const float* b_ff1      = (const float*)d_in[13];
    const float* W_ff2      = (const float*)d_in[14];
    const float* b_ff2      = (const float*)d_in[15];

    float* out1    = (float*)d_out;
    float* out_vel = out1 + BSD;

    __half *p_xn_h, *p_gate, *p_cc_h, *p_xnew_h, *p_nm_h, *p_hd_h, *p_wt_h;
    float *p_a, *p_splam;
    cudaGetSymbolAddress((void**)&p_xn_h, g_xn_h);
    cudaGetSymbolAddress((void**)&p_gate, g_gate);
    cudaGetSymbolAddress((void**)&p_a, g_a);
    cudaGetSymbolAddress((void**)&p_cc_h, g_cc_h);
    cudaGetSymbolAddress((void**)&p_xnew_h, g_xnew_h);
    cudaGetSymbolAddress((void**)&p_nm_h, g_nm_h);
    cudaGetSymbolAddress((void**)&p_hd_h, g_hd_h);
    cudaGetSymbolAddress((void**)&p_wt_h, g_wt_h);
    cudaGetSymbolAddress((void**)&p_splam, g_splam);

    cudaFuncSetAttribute(hgemm<1>, cudaFuncAttributeMaxDynamicSharedMemorySize, GEMM_SMEM);
    cudaFuncSetAttribute(hgemm<2>, cudaFuncAttributeMaxDynamicSharedMemorySize, GEMM_SMEM);
    cudaFuncSetAttribute(hgemm<3>, cudaFuncAttributeMaxDynamicSharedMemorySize, GEMM_SMEM);
    cudaFuncSetAttribute(hgemm<4>, cudaFuncAttributeMaxDynamicSharedMemorySize, GEMM_SMEM);
    constexpr int SCAN_SMEM = SLEN * 256 * sizeof(float2);   // 64 KB
    cudaFuncSetAttribute(gscan_one, cudaFuncAttributeMaxDynamicSharedMemorySize, SCAN_SMEM);

    // side stream + fork/join events (created per call; never destroyed while
    // capture may still reference them — tiny host-side leak over ~2 calls)
    cudaStream_t s_side;
    cudaEvent_t ev_fork, ev_j1, ev_j2;
    cudaStreamCreateWithFlags(&s_side, cudaStreamNonBlocking);
    cudaEventCreateWithFlags(&ev_fork, cudaEventDisableTiming);
    cudaEventCreateWithFlags(&ev_j1, cudaEventDisableTiming);
    cudaEventCreateWithFlags(&ev_j2, cudaEventDisableTiming);

    const size_t OFF_GA = 0, OFF_OUT = (size_t)2 << 20,
                 OFF_FF1 = (size_t)4 << 20, OFF_FF2 = (size_t)8 << 20;

    // fork side branch: weight transposes
    cudaEventRecord(ev_fork, 0);
    cudaStreamWaitEvent(s_side, ev_fork, 0);
    transpose_all<<<2048, 256, 0, s_side>>>(W_gate, W_a, W_out, W_ff1, W_ff2, p_wt_h, 0);
    cudaEventRecord(ev_j1, s_side);
    transpose_all<<<10240, 256, 0, s_side>>>(W_gate, W_a, W_out, W_ff1, W_ff2, p_wt_h, 2048);
    cudaEventRecord(ev_j2, s_side);

    // main stream: pre-norm + prologue (independent of transposes)
    rmsnorm_h<<<MM, 256>>>(x, pre_norm_w, p_xn_h);
    prologue<<<BB * SCH * DD / 256, 256>>>(lam);

    // join 1: gate/a weights ready
    cudaStreamWaitEvent(0, ev_j1, 0);

    // fused gate+a GEMM (M=8192, N=2048, K=1024) with gating epilogue
    dim3 gGA(2048 / 128, MM / 128);
    hgemm<4><<<gGA, 256, GEMM_SMEM>>>(p_xn_h, p_wt_h + OFF_GA,
                                      p_a, 2048, 1024,
                                      nullptr, nullptr, nullptr, p_splam, nullptr, p_gate);

    // single-pass conv + gating + scan (decoupled lookback)
    gscan_one<<<BB * SCH * (DD / 256), 256, SCAN_SMEM>>>(conv_k, conv_b);

    // join 2: remaining weights ready
    cudaStreamWaitEvent(0, ev_j2, 0);

    // mixer GEMM (K=2048) + velocity + residual (xnew -> fp16)
    dim3 gD(1024 / 128, MM / 128);
    hgemm<1><<<gD, 256, GEMM_SMEM>>>(p_cc_h, p_wt_h + OFF_OUT,
                                     out_vel, 1024, 2048,
                                     b_out, velocity, x, log_beta, p_xnew_h, nullptr);

    // ffn norm (fp16 in)
    rmsnorm_h16<<<MM, 256>>>(p_xnew_h, ffn_norm_w, p_nm_h);

    // ff1 + gelu -> fp16 hidden (N=4096, K=1024)
    dim3 gF(4096 / 128, MM / 128);
    hgemm<2><<<gF, 256, GEMM_SMEM>>>(p_nm_h, p_wt_h + OFF_FF1,
                                     nullptr, 4096, 1024,
                                     b_ff1, nullptr, nullptr, nullptr, p_hd_h, nullptr);

    // ff2 + fp16 residual (K=4096) -> out1
    hgemm<3><<<gD, 256, GEMM_SMEM>>>(p_hd_h, p_wt_h + OFF_FF2,
                                     out1, 1024, 4096,
                                     b_ff2, nullptr, nullptr, nullptr, nullptr, p_xnew_h);
}